// round 1
// baseline (speedup 1.0000x reference)
#include <cuda_runtime.h>

#define NNODES 10240
#define NGRAPH 64
#define HID 512
#define HEADS 8
#define HDIM 64
#define MAXC 384

// Scratch (device globals: no allocation allowed)
__device__ float g_Q[(size_t)NNODES * HID];
__device__ float g_K[(size_t)NNODES * HID];
__device__ float g_V[(size_t)NNODES * HID];
__device__ float g_O[(size_t)NNODES * HID];
__device__ int g_start[NGRAPH + 2];

// ---------------------------------------------------------------------------
// Segment starts from sorted batch array. Handles int32 or int64 storage:
// if int64, the int32 view's word (n-1) is the high half of element (n-1)/2
// which is 0; if int32, it's the last (max) graph id (>0 w.p. ~1).
// ---------------------------------------------------------------------------
__global__ void starts_kernel(const void* bptr, int n) {
    const int* b32 = (const int*)bptr;
    const long long* b64 = (const long long*)bptr;
    const bool is64 = (b32[n - 1] == 0);
    int i = blockIdx.x * blockDim.x + threadIdx.x;
    if (i >= n) return;
    int bi = is64 ? (int)b64[i] : b32[i];
    int bp = (i == 0) ? -1 : (is64 ? (int)b64[i - 1] : b32[i - 1]);
    for (int g = bp + 1; g <= bi; ++g) g_start[g] = i;
    if (i == n - 1) {
        for (int g = bi + 1; g <= NGRAPH; ++g) g_start[g] = n;
    }
}

// ---------------------------------------------------------------------------
// SGEMM: C[M,N] = A[M,K] * W[N,K]^T + bias[N]   (M=10240, N=K=512)
// 128x128 tile, BK=16, 256 threads, 8x8 per-thread microtile.
// ---------------------------------------------------------------------------
#define BM 128
#define BN 128
#define BK 16

__global__ __launch_bounds__(256, 1) void sgemm_bias(
    const float* __restrict__ A, const float* __restrict__ W,
    const float* __restrict__ bias, float* __restrict__ C)
{
    __shared__ float As[BK][BM + 4];
    __shared__ float Ws[BK][BN + 4];
    const int tid = threadIdx.x;
    const int bm = blockIdx.y * BM;
    const int bn = blockIdx.x * BN;
    const int lrow = tid >> 2;         // 0..63
    const int lcol = (tid & 3) * 4;    // 0,4,8,12
    const int ty = tid >> 4;           // 0..15 (M dir)
    const int tx = tid & 15;           // 0..15 (N dir)
    const float* Ap = A + (size_t)bm * HID;
    const float* Wp = W + (size_t)bn * HID;

    float acc[8][8];
#pragma unroll
    for (int i = 0; i < 8; i++)
#pragma unroll
        for (int j = 0; j < 8; j++) acc[i][j] = 0.f;

    for (int k0 = 0; k0 < HID; k0 += BK) {
#pragma unroll
        for (int r = 0; r < BM; r += 64) {
            float4 a4 = *(const float4*)(Ap + (size_t)(lrow + r) * HID + k0 + lcol);
            As[lcol + 0][lrow + r] = a4.x;
            As[lcol + 1][lrow + r] = a4.y;
            As[lcol + 2][lrow + r] = a4.z;
            As[lcol + 3][lrow + r] = a4.w;
        }
#pragma unroll
        for (int r = 0; r < BN; r += 64) {
            float4 w4 = *(const float4*)(Wp + (size_t)(lrow + r) * HID + k0 + lcol);
            Ws[lcol + 0][lrow + r] = w4.x;
            Ws[lcol + 1][lrow + r] = w4.y;
            Ws[lcol + 2][lrow + r] = w4.z;
            Ws[lcol + 3][lrow + r] = w4.w;
        }
        __syncthreads();
#pragma unroll
        for (int k = 0; k < BK; k++) {
            float4 a0 = *(const float4*)&As[k][ty * 8];
            float4 a1 = *(const float4*)&As[k][ty * 8 + 4];
            float4 w0 = *(const float4*)&Ws[k][tx * 8];
            float4 w1 = *(const float4*)&Ws[k][tx * 8 + 4];
            float ra[8] = {a0.x, a0.y, a0.z, a0.w, a1.x, a1.y, a1.z, a1.w};
            float rw[8] = {w0.x, w0.y, w0.z, w0.w, w1.x, w1.y, w1.z, w1.w};
#pragma unroll
            for (int i = 0; i < 8; i++)
#pragma unroll
                for (int j = 0; j < 8; j++)
                    acc[i][j] += ra[i] * rw[j];
        }
        __syncthreads();
    }

    float4 b0 = *(const float4*)(bias + bn + tx * 8);
    float4 b1 = *(const float4*)(bias + bn + tx * 8 + 4);
#pragma unroll
    for (int i = 0; i < 8; i++) {
        int row = bm + ty * 8 + i;
        float* cp = C + (size_t)row * HID + bn + tx * 8;
        float4 o0 = make_float4(acc[i][0] + b0.x, acc[i][1] + b0.y,
                                acc[i][2] + b0.z, acc[i][3] + b0.w);
        float4 o1 = make_float4(acc[i][4] + b1.x, acc[i][5] + b1.y,
                                acc[i][6] + b1.z, acc[i][7] + b1.w);
        *(float4*)cp = o0;
        *(float4*)(cp + 4) = o1;
    }
}

// ---------------------------------------------------------------------------
// Attention: one block per (graph, head). K,V for the graph live in smem.
// One thread per query; q and o in registers; two-pass softmax.
// ---------------------------------------------------------------------------
__global__ __launch_bounds__(256, 1) void attn_kernel(
    const float* __restrict__ Q, const float* __restrict__ K,
    const float* __restrict__ V, float* __restrict__ O)
{
    extern __shared__ float sm[];
    float* Ksh = sm;                  // [MAXC][HDIM]
    float* Vsh = sm + MAXC * HDIM;    // [MAXC][HDIM]
    const int g = blockIdx.x;
    const int h = blockIdx.y;
    const int st = g_start[g];
    const int c = g_start[g + 1] - st;
    if (c <= 0) return;
    const int tid = threadIdx.x;
    const size_t base = (size_t)st * HID + h * HDIM;

    for (int idx = tid; idx < c * (HDIM / 4); idx += blockDim.x) {
        int r = idx >> 4;
        int d4 = (idx & 15) << 2;
        *(float4*)(Ksh + r * HDIM + d4) = *(const float4*)(K + base + (size_t)r * HID + d4);
        *(float4*)(Vsh + r * HDIM + d4) = *(const float4*)(V + base + (size_t)r * HID + d4);
    }
    __syncthreads();

    const float scale = 0.125f;  // 1/sqrt(64)
    for (int q = tid; q < c; q += blockDim.x) {
        float4 qv[16];
        const float4* qp = (const float4*)(Q + base + (size_t)q * HID);
#pragma unroll
        for (int d = 0; d < 16; d++) qv[d] = qp[d];

        // pass 1: row max of logits
        float m = -3.0e38f;
        for (int j = 0; j < c; j++) {
            const float4* kr = (const float4*)(Ksh + j * HDIM);
            float sa = 0.f, sb = 0.f, sc = 0.f, sd = 0.f;
#pragma unroll
            for (int d = 0; d < 16; d += 4) {
                float4 k0 = kr[d], k1 = kr[d + 1], k2 = kr[d + 2], k3 = kr[d + 3];
                sa += qv[d].x * k0.x + qv[d].y * k0.y + qv[d].z * k0.z + qv[d].w * k0.w;
                sb += qv[d + 1].x * k1.x + qv[d + 1].y * k1.y + qv[d + 1].z * k1.z + qv[d + 1].w * k1.w;
                sc += qv[d + 2].x * k2.x + qv[d + 2].y * k2.y + qv[d + 2].z * k2.z + qv[d + 2].w * k2.w;
                sd += qv[d + 3].x * k3.x + qv[d + 3].y * k3.y + qv[d + 3].z * k3.z + qv[d + 3].w * k3.w;
            }
            float s = (sa + sb) + (sc + sd);
            m = fmaxf(m, s);
        }
        m *= scale;

        // pass 2: exp-sum and weighted V accumulation
        float l = 0.f;
        float4 o[16];
#pragma unroll
        for (int d = 0; d < 16; d++) o[d] = make_float4(0.f, 0.f, 0.f, 0.f);
        for (int j = 0; j < c; j++) {
            const float4* kr = (const float4*)(Ksh + j * HDIM);
            float sa = 0.f, sb = 0.f, sc = 0.f, sd = 0.f;
#pragma unroll
            for (int d = 0; d < 16; d += 4) {
                float4 k0 = kr[d], k1 = kr[d + 1], k2 = kr[d + 2], k3 = kr[d + 3];
                sa += qv[d].x * k0.x + qv[d].y * k0.y + qv[d].z * k0.z + qv[d].w * k0.w;
                sb += qv[d + 1].x * k1.x + qv[d + 1].y * k1.y + qv[d + 1].z * k1.z + qv[d + 1].w * k1.w;
                sc += qv[d + 2].x * k2.x + qv[d + 2].y * k2.y + qv[d + 2].z * k2.z + qv[d + 2].w * k2.w;
                sd += qv[d + 3].x * k3.x + qv[d + 3].y * k3.y + qv[d + 3].z * k3.z + qv[d + 3].w * k3.w;
            }
            float s = (sa + sb) + (sc + sd);
            float p = __expf(s * scale - m);
            l += p;
            const float4* vr = (const float4*)(Vsh + j * HDIM);
#pragma unroll
            for (int d = 0; d < 16; d++) {
                float4 v4 = vr[d];
                o[d].x += p * v4.x;
                o[d].y += p * v4.y;
                o[d].z += p * v4.z;
                o[d].w += p * v4.w;
            }
        }
        float inv = 1.f / l;
        float* op = O + base + (size_t)q * HID;
#pragma unroll
        for (int d = 0; d < 16; d++) {
            *(float4*)(op + d * 4) =
                make_float4(o[d].x * inv, o[d].y * inv, o[d].z * inv, o[d].w * inv);
        }
    }
}

// ---------------------------------------------------------------------------
extern "C" void kernel_launch(void* const* d_in, const int* in_sizes, int n_in,
                              void* d_out, int out_size) {
    const float* x  = (const float*)d_in[0];
    const void*  bt = d_in[1];
    const float* wq = (const float*)d_in[2];
    const float* bq = (const float*)d_in[3];
    const float* wk = (const float*)d_in[4];
    const float* bk = (const float*)d_in[5];
    const float* wv = (const float*)d_in[6];
    const float* bv = (const float*)d_in[7];
    const float* wo = (const float*)d_in[8];
    const float* bo = (const float*)d_in[9];
    float* out = (float*)d_out;

    float *Qb, *Kb, *Vb, *Ob;
    cudaGetSymbolAddress((void**)&Qb, g_Q);
    cudaGetSymbolAddress((void**)&Kb, g_K);
    cudaGetSymbolAddress((void**)&Vb, g_V);
    cudaGetSymbolAddress((void**)&Ob, g_O);

    starts_kernel<<<(NNODES + 255) / 256, 256>>>(bt, NNODES);

    dim3 ggrid(HID / BN, NNODES / BM);  // (4, 80)
    sgemm_bias<<<ggrid, 256>>>(x, wq, bq, Qb);
    sgemm_bias<<<ggrid, 256>>>(x, wk, bk, Kb);
    sgemm_bias<<<ggrid, 256>>>(x, wv, bv, Vb);

    const int smem = 2 * MAXC * HDIM * (int)sizeof(float);  // 192 KB
    cudaFuncSetAttribute(attn_kernel, cudaFuncAttributeMaxDynamicSharedMemorySize, smem);
    attn_kernel<<<dim3(NGRAPH, HEADS), 256, smem>>>(Qb, Kb, Vb, Ob);

    sgemm_bias<<<ggrid, 256>>>(Ob, wo, bo, out);
}

// round 4
// speedup vs baseline: 1.7719x; 1.7719x over previous
#include <cuda_runtime.h>
#include <cuda_fp16.h>
#include <cstdint>

#define NNODES 10240
#define NGRAPH 64
#define HID 512
#define HEADS 8
#define HDIM 64
#define MAXC 384

#define KE 1536              // expanded K: A=[hi|lo|hi], B=[hi|hi|lo]
#define KC 64                // halves per K-chunk (128B per row)
#define NKCH (KE / KC)       // 24
#define ROWB 144             // smem row stride in bytes (128 + 16 pad)
#define STG_B (128 * ROWB)   // 18432 bytes per tile
#define STAGE_B (2 * STG_B)  // A + B per stage = 36864
#define GEMM_SMEM (2 * STAGE_B)  // 73728

// ---------------------------------------------------------------------------
// Scratch (device globals: no allocation allowed)
// ---------------------------------------------------------------------------
__device__ float g_Q[(size_t)NNODES * HID];
__device__ float g_K[(size_t)NNODES * HID];
__device__ float g_V[(size_t)NNODES * HID];
__device__ float g_O[(size_t)NNODES * HID];
__device__ __align__(16) __half g_Xe[(size_t)NNODES * KE];
__device__ __align__(16) __half g_We[4][(size_t)HID * KE];
__device__ int g_start[NGRAPH + 2];

// ---------------------------------------------------------------------------
__device__ __forceinline__ uint32_t smem_u32(const void* p) {
    uint32_t a;
    asm("{ .reg .u64 t; cvta.to.shared.u64 t, %1; cvt.u32.u64 %0, t; }" : "=r"(a) : "l"(p));
    return a;
}

// ---------------------------------------------------------------------------
// Segment starts from sorted batch (int32 or int64 storage).
// ---------------------------------------------------------------------------
__global__ void starts_kernel(const void* bptr, int n) {
    const int* b32 = (const int*)bptr;
    const long long* b64 = (const long long*)bptr;
    const bool is64 = (b32[n - 1] == 0);
    int i = blockIdx.x * blockDim.x + threadIdx.x;
    if (i >= n) return;
    int bi = is64 ? (int)b64[i] : b32[i];
    int bp = (i == 0) ? -1 : (is64 ? (int)b64[i - 1] : b32[i - 1]);
    for (int g = bp + 1; g <= bi; ++g) g_start[g] = i;
    if (i == n - 1)
        for (int g = bi + 1; g <= NGRAPH; ++g) g_start[g] = n;
}

// ---------------------------------------------------------------------------
// fp32 -> fp16 hi/lo expansion.
// A layout [hi | lo | hi]; B layout [hi | hi | lo]:
// sum over K gives hi*hi + lo*hi + hi*lo  (missing lo*lo ~ 2^-22)
// ---------------------------------------------------------------------------
__global__ void expand_a(const float* __restrict__ X, __half* __restrict__ Xe, int total) {
    int i = blockIdx.x * blockDim.x + threadIdx.x;
    if (i >= total) return;
    int r = i >> 9, c = i & 511;
    float v = X[i];
    __half h = __float2half(v);
    __half l = __float2half(v - __half2float(h));
    size_t b = (size_t)r * KE;
    Xe[b + c] = h; Xe[b + 512 + c] = l; Xe[b + 1024 + c] = h;
}
__global__ void expand_b(const float* __restrict__ W, __half* __restrict__ We, int total) {
    int i = blockIdx.x * blockDim.x + threadIdx.x;
    if (i >= total) return;
    int r = i >> 9, c = i & 511;
    float v = W[i];
    __half h = __float2half(v);
    __half l = __float2half(v - __half2float(h));
    size_t b = (size_t)r * KE;
    We[b + c] = h; We[b + 512 + c] = h; We[b + 1024 + c] = l;
}

// ---------------------------------------------------------------------------
// HMMA GEMM: C[M,512] = Ae[M,1536] * Be[512,1536]^T + bias   (fp16 in, fp32 acc)
// 128x128 CTA tile, 8 warps (2m x 4n), warp tile 64x32, mma.sync.m16n8k16.
// cp.async double-buffered smem. B stored [n][k] (k contiguous) == col-major
// k x n, so BOTH A and B fragments use non-trans ldmatrix.
// ---------------------------------------------------------------------------
__global__ __launch_bounds__(256, 2) void gemm_hmma(
    const __half* __restrict__ A, const __half* __restrict__ B,
    const float* __restrict__ bias, float* __restrict__ C)
{
    extern __shared__ char sm_raw[];
    const int tid = threadIdx.x;
    const int wid = tid >> 5, lane = tid & 31;
    const int bm = blockIdx.y * 128, bn = blockIdx.x * 128;
    const int wm = (wid & 1) * 64;     // warp m offset in tile
    const int wn = (wid >> 1) * 32;    // warp n offset in tile

    const uint32_t sbase = smem_u32(sm_raw);

    float acc[4][4][4];
#pragma unroll
    for (int a = 0; a < 4; a++)
#pragma unroll
        for (int b = 0; b < 4; b++)
#pragma unroll
            for (int c = 0; c < 4; c++) acc[a][b][c] = 0.f;

    const int lr = tid >> 3;      // 0..31 load row group
    const int ls = tid & 7;       // 0..7 16B segment

    // prologue: stage 0
    {
        const __half* gA = A + (size_t)bm * KE + 0 * KC;
        const __half* gB = B + (size_t)bn * KE + 0 * KC;
        uint32_t sA = sbase, sB = sbase + STG_B;
#pragma unroll
        for (int t = 0; t < 4; t++) {
            int row = lr + t * 32;
            asm volatile("cp.async.cg.shared.global [%0], [%1], 16;"
                         :: "r"(sA + row * ROWB + ls * 16), "l"(gA + (size_t)row * KE + ls * 8));
            asm volatile("cp.async.cg.shared.global [%0], [%1], 16;"
                         :: "r"(sB + row * ROWB + ls * 16), "l"(gB + (size_t)row * KE + ls * 8));
        }
        asm volatile("cp.async.commit_group;");
    }

    for (int ch = 0; ch < NKCH; ++ch) {
        const int s = ch & 1;
        if (ch + 1 < NKCH) {
            const int s2 = (ch + 1) & 1;
            const __half* gA = A + (size_t)bm * KE + (ch + 1) * KC;
            const __half* gB = B + (size_t)bn * KE + (ch + 1) * KC;
            uint32_t sA = sbase + s2 * STAGE_B, sB = sA + STG_B;
#pragma unroll
            for (int t = 0; t < 4; t++) {
                int row = lr + t * 32;
                asm volatile("cp.async.cg.shared.global [%0], [%1], 16;"
                             :: "r"(sA + row * ROWB + ls * 16), "l"(gA + (size_t)row * KE + ls * 8));
                asm volatile("cp.async.cg.shared.global [%0], [%1], 16;"
                             :: "r"(sB + row * ROWB + ls * 16), "l"(gB + (size_t)row * KE + ls * 8));
            }
            asm volatile("cp.async.commit_group;");
            asm volatile("cp.async.wait_group 1;");
        } else {
            asm volatile("cp.async.wait_group 0;");
        }
        __syncthreads();

        const uint32_t sA = sbase + s * STAGE_B;
        const uint32_t sB = sA + STG_B;
        const int lrow = lane & 15;
        const int lcol = (lane >> 4) * 8;   // halves

#pragma unroll
        for (int k = 0; k < KC; k += 16) {
            uint32_t ar[4][4];
#pragma unroll
            for (int mt = 0; mt < 4; mt++) {
                uint32_t addr = sA + (wm + mt * 16 + lrow) * ROWB + (k + lcol) * 2;
                asm volatile("ldmatrix.sync.aligned.m8n8.x4.shared.b16 {%0,%1,%2,%3}, [%4];"
                             : "=r"(ar[mt][0]), "=r"(ar[mt][1]), "=r"(ar[mt][2]), "=r"(ar[mt][3])
                             : "r"(addr));
            }
            uint32_t br[2][4];
#pragma unroll
            for (int nt2 = 0; nt2 < 2; nt2++) {
                uint32_t addr = sB + (wn + nt2 * 16 + lrow) * ROWB + (k + lcol) * 2;
                asm volatile("ldmatrix.sync.aligned.m8n8.x4.shared.b16 {%0,%1,%2,%3}, [%4];"
                             : "=r"(br[nt2][0]), "=r"(br[nt2][1]), "=r"(br[nt2][2]), "=r"(br[nt2][3])
                             : "r"(addr));
            }
#pragma unroll
            for (int mt = 0; mt < 4; mt++)
#pragma unroll
                for (int nt = 0; nt < 4; nt++) {
                    uint32_t b0 = br[nt >> 1][nt & 1];
                    uint32_t b1 = br[nt >> 1][(nt & 1) + 2];
                    asm volatile(
                        "mma.sync.aligned.m16n8k16.row.col.f32.f16.f16.f32 "
                        "{%0,%1,%2,%3}, {%4,%5,%6,%7}, {%8,%9}, {%0,%1,%2,%3};"
                        : "+f"(acc[mt][nt][0]), "+f"(acc[mt][nt][1]),
                          "+f"(acc[mt][nt][2]), "+f"(acc[mt][nt][3])
                        : "r"(ar[mt][0]), "r"(ar[mt][1]), "r"(ar[mt][2]), "r"(ar[mt][3]),
                          "r"(b0), "r"(b1));
                }
        }
        __syncthreads();
    }

    // epilogue: c-frag layout: rows mt*16 + (lane>>2) + {0,8}; cols nt*8 + (lane&3)*2 + {0,1}
    const int r0 = bm + wm + (lane >> 2);
    const int c0base = bn + wn + (lane & 3) * 2;
#pragma unroll
    for (int nt = 0; nt < 4; nt++) {
        int col = c0base + nt * 8;
        float2 bb = *(const float2*)(bias + col);
#pragma unroll
        for (int mt = 0; mt < 4; mt++) {
            int row = r0 + mt * 16;
            *(float2*)(C + (size_t)row * HID + col) =
                make_float2(acc[mt][nt][0] + bb.x, acc[mt][nt][1] + bb.y);
            *(float2*)(C + (size_t)(row + 8) * HID + col) =
                make_float2(acc[mt][nt][2] + bb.x, acc[mt][nt][3] + bb.y);
        }
    }
}

// ---------------------------------------------------------------------------
// Attention: one block per (graph, head); K,V in smem; one thread per query;
// single-pass softmax without max subtraction (|logit| small, fp32-safe).
// ---------------------------------------------------------------------------
__global__ __launch_bounds__(256, 1) void attn_kernel(
    const float* __restrict__ Q, const float* __restrict__ K,
    const float* __restrict__ V, float* __restrict__ O)
{
    extern __shared__ float sm[];
    float* Ksh = sm;
    float* Vsh = sm + MAXC * HDIM;
    const int g = blockIdx.x;
    const int h = blockIdx.y;
    const int st = g_start[g];
    const int c = g_start[g + 1] - st;
    if (c <= 0) return;
    const int tid = threadIdx.x;
    const size_t base = (size_t)st * HID + h * HDIM;

    for (int idx = tid; idx < c * (HDIM / 4); idx += blockDim.x) {
        int r = idx >> 4;
        int d4 = (idx & 15) << 2;
        *(float4*)(Ksh + r * HDIM + d4) = *(const float4*)(K + base + (size_t)r * HID + d4);
        *(float4*)(Vsh + r * HDIM + d4) = *(const float4*)(V + base + (size_t)r * HID + d4);
    }
    __syncthreads();

    const float scale = 0.125f;  // 1/sqrt(64)
    for (int q = tid; q < c; q += blockDim.x) {
        float4 qv[16];
        const float4* qp = (const float4*)(Q + base + (size_t)q * HID);
#pragma unroll
        for (int d = 0; d < 16; d++) qv[d] = qp[d];

        float l = 0.f;
        float4 o[16];
#pragma unroll
        for (int d = 0; d < 16; d++) o[d] = make_float4(0.f, 0.f, 0.f, 0.f);

        for (int j = 0; j < c; j++) {
            const float4* kr = (const float4*)(Ksh + j * HDIM);
            float sa = 0.f, sb = 0.f, sc = 0.f, sd = 0.f;
#pragma unroll
            for (int d = 0; d < 16; d += 4) {
                float4 k0 = kr[d], k1 = kr[d + 1], k2 = kr[d + 2], k3 = kr[d + 3];
                sa += qv[d].x * k0.x + qv[d].y * k0.y + qv[d].z * k0.z + qv[d].w * k0.w;
                sb += qv[d + 1].x * k1.x + qv[d + 1].y * k1.y + qv[d + 1].z * k1.z + qv[d + 1].w * k1.w;
                sc += qv[d + 2].x * k2.x + qv[d + 2].y * k2.y + qv[d + 2].z * k2.z + qv[d + 2].w * k2.w;
                sd += qv[d + 3].x * k3.x + qv[d + 3].y * k3.y + qv[d + 3].z * k3.z + qv[d + 3].w * k3.w;
            }
            float s = ((sa + sb) + (sc + sd)) * scale;
            float p = __expf(fminf(s, 80.f));
            l += p;
            const float4* vr = (const float4*)(Vsh + j * HDIM);
#pragma unroll
            for (int d = 0; d < 16; d++) {
                float4 v4 = vr[d];
                o[d].x += p * v4.x; o[d].y += p * v4.y;
                o[d].z += p * v4.z; o[d].w += p * v4.w;
            }
        }
        float inv = 1.f / l;
        float* op = O + base + (size_t)q * HID;
#pragma unroll
        for (int d = 0; d < 16; d++)
            *(float4*)(op + d * 4) =
                make_float4(o[d].x * inv, o[d].y * inv, o[d].z * inv, o[d].w * inv);
    }
}

// ---------------------------------------------------------------------------
extern "C" void kernel_launch(void* const* d_in, const int* in_sizes, int n_in,
                              void* d_out, int out_size) {
    const float* x  = (const float*)d_in[0];
    const void*  bt = d_in[1];
    const float* wq = (const float*)d_in[2];
    const float* bq = (const float*)d_in[3];
    const float* wk = (const float*)d_in[4];
    const float* bk = (const float*)d_in[5];
    const float* wv = (const float*)d_in[6];
    const float* bv = (const float*)d_in[7];
    const float* wo = (const float*)d_in[8];
    const float* bo = (const float*)d_in[9];
    float* out = (float*)d_out;

    float *Qb, *Kb, *Vb, *Ob;
    __half *Xe, *We;
    cudaGetSymbolAddress((void**)&Qb, g_Q);
    cudaGetSymbolAddress((void**)&Kb, g_K);
    cudaGetSymbolAddress((void**)&Vb, g_V);
    cudaGetSymbolAddress((void**)&Ob, g_O);
    cudaGetSymbolAddress((void**)&Xe, g_Xe);
    cudaGetSymbolAddress((void**)&We, g_We);
    __half* Weq = We;
    __half* Wek = We + (size_t)HID * KE;
    __half* Wev = We + 2 * (size_t)HID * KE;
    __half* Weo = We + 3 * (size_t)HID * KE;

    cudaFuncSetAttribute(gemm_hmma, cudaFuncAttributeMaxDynamicSharedMemorySize, GEMM_SMEM);
    const int attn_smem = 2 * MAXC * HDIM * (int)sizeof(float);  // 192 KB
    cudaFuncSetAttribute(attn_kernel, cudaFuncAttributeMaxDynamicSharedMemorySize, attn_smem);

    starts_kernel<<<(NNODES + 255) / 256, 256>>>(bt, NNODES);

    const int xtot = NNODES * HID, wtot = HID * HID;
    expand_a<<<(xtot + 255) / 256, 256>>>(x, Xe, xtot);
    expand_b<<<(wtot + 255) / 256, 256>>>(wq, Weq, wtot);
    expand_b<<<(wtot + 255) / 256, 256>>>(wk, Wek, wtot);
    expand_b<<<(wtot + 255) / 256, 256>>>(wv, Wev, wtot);
    expand_b<<<(wtot + 255) / 256, 256>>>(wo, Weo, wtot);

    dim3 ggrid(HID / 128, NNODES / 128);  // (4, 80)
    gemm_hmma<<<ggrid, 256, GEMM_SMEM>>>(Xe, Weq, bq, Qb);
    gemm_hmma<<<ggrid, 256, GEMM_SMEM>>>(Xe, Wek, bk, Kb);
    gemm_hmma<<<ggrid, 256, GEMM_SMEM>>>(Xe, Wev, bv, Vb);

    attn_kernel<<<dim3(NGRAPH, HEADS), 256, attn_smem>>>(Qb, Kb, Vb, Ob);

    expand_a<<<(xtot + 255) / 256, 256>>>(Ob, Xe, xtot);
    gemm_hmma<<<ggrid, 256, GEMM_SMEM>>>(Xe, Weo, bo, out);
}

// round 5
// speedup vs baseline: 2.0200x; 1.1400x over previous
#include <cuda_runtime.h>
#include <cuda_fp16.h>
#include <cstdint>

#define NNODES 10240
#define NGRAPH 64
#define HID 512
#define HEADS 8
#define HDIM 64
#define MAXC 384

#define KE 1536              // expanded K: A=[hi|lo|hi], B=[hi|hi|lo]
#define KC 64                // halves per K-chunk (128B per row)
#define NKCH (KE / KC)       // 24
#define STG 16384            // bytes per tile (128 rows x 128B, swizzled, no pad)
#define STAGE (2 * STG)      // A + B per stage = 32768
#define NSTAGE 3
#define GEMM_SMEM (NSTAGE * STAGE)   // 98304

// ---------------------------------------------------------------------------
// Scratch (device globals: no allocation allowed)
// ---------------------------------------------------------------------------
__device__ float g_QKV[(size_t)NNODES * 3 * HID];                 // fused Q|K|V
__device__ __align__(16) __half g_Xe[(size_t)NNODES * KE];        // x / O expanded
__device__ __align__(16) __half g_We[4][(size_t)HID * KE];        // wq,wk,wv,wo expanded
__device__ float g_bcat[3 * HID];
__device__ int g_start[NGRAPH + 2];

// ---------------------------------------------------------------------------
__device__ __forceinline__ uint32_t smem_u32(const void* p) {
    uint32_t a;
    asm("{ .reg .u64 t; cvta.to.shared.u64 t, %1; cvt.u32.u64 %0, t; }" : "=r"(a) : "l"(p));
    return a;
}

// ---------------------------------------------------------------------------
// Segment starts from sorted batch (int32 or int64 storage).
// ---------------------------------------------------------------------------
__global__ void starts_kernel(const void* bptr, int n) {
    const int* b32 = (const int*)bptr;
    const long long* b64 = (const long long*)bptr;
    const bool is64 = (b32[n - 1] == 0);
    int i = blockIdx.x * blockDim.x + threadIdx.x;
    if (i >= n) return;
    int bi = is64 ? (int)b64[i] : b32[i];
    int bp = (i == 0) ? -1 : (is64 ? (int)b64[i - 1] : b32[i - 1]);
    for (int g = bp + 1; g <= bi; ++g) g_start[g] = i;
    if (i == n - 1)
        for (int g = bi + 1; g <= NGRAPH; ++g) g_start[g] = n;
}

__global__ void bias_cat(const float* bq, const float* bk, const float* bv) {
    int i = threadIdx.x;
    g_bcat[i] = bq[i];
    g_bcat[HID + i] = bk[i];
    g_bcat[2 * HID + i] = bv[i];
}

// ---------------------------------------------------------------------------
// fp32 -> fp16 hi/lo expansion.  A layout [hi|lo|hi]; B layout [hi|hi|lo]:
// sum over expanded K gives hi*hi + lo*hi + hi*lo (missing lo*lo ~ 2^-22).
// ---------------------------------------------------------------------------
__global__ void expand_a(const float* __restrict__ X, __half* __restrict__ Xe, int total) {
    int i = blockIdx.x * blockDim.x + threadIdx.x;
    if (i >= total) return;
    int r = i >> 9, c = i & 511;
    float v = X[i];
    __half h = __float2half(v);
    __half l = __float2half(v - __half2float(h));
    size_t b = (size_t)r * KE;
    Xe[b + c] = h; Xe[b + 512 + c] = l; Xe[b + 1024 + c] = h;
}

__global__ void expand_w4(const float* __restrict__ w0, const float* __restrict__ w1,
                          const float* __restrict__ w2, const float* __restrict__ w3,
                          __half* __restrict__ We) {
    int i = blockIdx.x * blockDim.x + threadIdx.x;
    if (i >= 4 * HID * HID) return;
    int m = i >> 18;
    int local = i & 262143;
    const float* W = (m == 0) ? w0 : (m == 1) ? w1 : (m == 2) ? w2 : w3;
    int r = local >> 9, c = local & 511;
    float v = W[r * HID + c];
    __half h = __float2half(v);
    __half l = __float2half(v - __half2float(h));
    size_t b = (size_t)m * HID * KE + (size_t)r * KE;
    We[b + c] = h; We[b + 512 + c] = h; We[b + 1024 + c] = l;
}

// ---------------------------------------------------------------------------
// HMMA GEMM: C[M, N] = Ae[M,1536] * Be[N,1536]^T + bias  (fp16 in, fp32 acc)
// 128x128 CTA tile, 8 warps (2m x 4n), mma.sync.m16n8k16, XOR-swizzled smem,
// 3-stage cp.async ring, ONE __syncthreads per K-chunk.
// ---------------------------------------------------------------------------
__global__ __launch_bounds__(256, 2) void gemm_hmma(
    const __half* __restrict__ A, const __half* __restrict__ B,
    const float* __restrict__ bias, float* __restrict__ C, int ldc)
{
    extern __shared__ char sm_raw[];
    const int tid = threadIdx.x;
    const int wid = tid >> 5, lane = tid & 31;
    const int bm = blockIdx.y * 128, bn = blockIdx.x * 128;
    const int wm = (wid & 1) * 64;
    const int wn = (wid >> 1) * 32;
    const uint32_t sbase = smem_u32(sm_raw);

    float acc[4][4][4];
#pragma unroll
    for (int a = 0; a < 4; a++)
#pragma unroll
        for (int b = 0; b < 4; b++)
#pragma unroll
            for (int c = 0; c < 4; c++) acc[a][b][c] = 0.f;

    const int lr = tid >> 3;     // 0..31 row group
    const int ls = tid & 7;      // 0..7 16B segment

    auto issue = [&](int ch) {
        const __half* gA = A + (size_t)bm * KE + ch * KC;
        const __half* gB = B + (size_t)bn * KE + ch * KC;
        uint32_t sA = sbase + (ch % NSTAGE) * STAGE;
        uint32_t sB = sA + STG;
#pragma unroll
        for (int t = 0; t < 4; t++) {
            int row = lr + t * 32;
            uint32_t off = row * 128 + ((ls ^ (row & 7)) * 16);
            asm volatile("cp.async.cg.shared.global [%0], [%1], 16;"
                         :: "r"(sA + off), "l"(gA + (size_t)row * KE + ls * 8));
            asm volatile("cp.async.cg.shared.global [%0], [%1], 16;"
                         :: "r"(sB + off), "l"(gB + (size_t)row * KE + ls * 8));
        }
        asm volatile("cp.async.commit_group;");
    };

    issue(0);
    issue(1);

    const int lrow = lane & 15;
    const int lseg = lane >> 4;    // 0/1: +8 halves

    for (int ch = 0; ch < NKCH; ++ch) {
        if (ch < NKCH - 1) asm volatile("cp.async.wait_group 1;");
        else               asm volatile("cp.async.wait_group 0;");
        __syncthreads();
        if (ch + 2 < NKCH) issue(ch + 2);

        const uint32_t sA = sbase + (ch % NSTAGE) * STAGE;
        const uint32_t sB = sA + STG;

#pragma unroll
        for (int k = 0; k < KC; k += 16) {
            const int seg = (k >> 3) + lseg;   // 16B segment within row
            uint32_t ar[4][4];
#pragma unroll
            for (int mt = 0; mt < 4; mt++) {
                int row = wm + mt * 16 + lrow;
                uint32_t addr = sA + row * 128 + ((seg ^ (row & 7)) * 16);
                asm volatile("ldmatrix.sync.aligned.m8n8.x4.shared.b16 {%0,%1,%2,%3}, [%4];"
                             : "=r"(ar[mt][0]), "=r"(ar[mt][1]), "=r"(ar[mt][2]), "=r"(ar[mt][3])
                             : "r"(addr));
            }
            uint32_t br[2][4];
#pragma unroll
            for (int nt2 = 0; nt2 < 2; nt2++) {
                int row = wn + nt2 * 16 + lrow;
                uint32_t addr = sB + row * 128 + ((seg ^ (row & 7)) * 16);
                asm volatile("ldmatrix.sync.aligned.m8n8.x4.shared.b16 {%0,%1,%2,%3}, [%4];"
                             : "=r"(br[nt2][0]), "=r"(br[nt2][1]), "=r"(br[nt2][2]), "=r"(br[nt2][3])
                             : "r"(addr));
            }
#pragma unroll
            for (int mt = 0; mt < 4; mt++)
#pragma unroll
                for (int nt = 0; nt < 4; nt++) {
                    uint32_t b0 = br[nt >> 1][nt & 1];
                    uint32_t b1 = br[nt >> 1][(nt & 1) + 2];
                    asm volatile(
                        "mma.sync.aligned.m16n8k16.row.col.f32.f16.f16.f32 "
                        "{%0,%1,%2,%3}, {%4,%5,%6,%7}, {%8,%9}, {%0,%1,%2,%3};"
                        : "+f"(acc[mt][nt][0]), "+f"(acc[mt][nt][1]),
                          "+f"(acc[mt][nt][2]), "+f"(acc[mt][nt][3])
                        : "r"(ar[mt][0]), "r"(ar[mt][1]), "r"(ar[mt][2]), "r"(ar[mt][3]),
                          "r"(b0), "r"(b1));
                }
        }
        __syncthreads();
    }

    const int r0 = bm + wm + (lane >> 2);
    const int c0base = bn + wn + (lane & 3) * 2;
#pragma unroll
    for (int nt = 0; nt < 4; nt++) {
        int col = c0base + nt * 8;
        float2 bb = *(const float2*)(bias + col);
#pragma unroll
        for (int mt = 0; mt < 4; mt++) {
            int row = r0 + mt * 16;
            *(float2*)(C + (size_t)row * ldc + col) =
                make_float2(acc[mt][nt][0] + bb.x, acc[mt][nt][1] + bb.y);
            *(float2*)(C + (size_t)(row + 8) * ldc + col) =
                make_float2(acc[mt][nt][2] + bb.x, acc[mt][nt][3] + bb.y);
        }
    }
}

// ---------------------------------------------------------------------------
// Attention: one block per (graph, head). K,V in smem. Each group of 4 lanes
// handles 4 queries; lane owns 16 of 64 dims. Partial dots reduced via
// shfl_xor butterfly. Single-pass softmax (no max subtraction; logits small).
// Output written directly in fp16 [hi|lo|hi] expanded layout into g_Xe.
// ---------------------------------------------------------------------------
__global__ __launch_bounds__(256, 1) void attn_kernel(
    const float* __restrict__ QKV, __half* __restrict__ Xe)
{
    extern __shared__ float sm[];
    float* Ksh = sm;                 // [c][64]
    float* Vsh = sm + MAXC * HDIM;
    const int g = blockIdx.x;
    const int h = blockIdx.y;
    const int st = g_start[g];
    const int c = g_start[g + 1] - st;
    if (c <= 0) return;
    const int tid = threadIdx.x;

    const float* baseQ = QKV + (size_t)st * 1536 + h * HDIM;
    const float* baseK = baseQ + 512;
    const float* baseV = baseQ + 1024;

    for (int idx = tid; idx < c * 16; idx += 256) {
        int r = idx >> 4;
        int d4 = (idx & 15) << 2;
        *(float4*)(Ksh + r * HDIM + d4) = *(const float4*)(baseK + (size_t)r * 1536 + d4);
        *(float4*)(Vsh + r * HDIM + d4) = *(const float4*)(baseV + (size_t)r * 1536 + d4);
    }
    __syncthreads();

    const int grp = tid >> 2;        // 0..63
    const int sub = tid & 3;         // dim slice
    const int d0 = sub * 16;
    const float scale = 0.125f;      // 1/sqrt(64)

    for (int qb = 0; qb < c; qb += 256) {
        const int q0 = qb + grp * 4;

        float qreg[4][16];
#pragma unroll
        for (int qi = 0; qi < 4; qi++) {
            int qq = min(q0 + qi, c - 1);
            const float4* qp = (const float4*)(baseQ + (size_t)qq * 1536 + d0);
#pragma unroll
            for (int t = 0; t < 4; t++) {
                float4 v = qp[t];
                qreg[qi][t * 4 + 0] = v.x; qreg[qi][t * 4 + 1] = v.y;
                qreg[qi][t * 4 + 2] = v.z; qreg[qi][t * 4 + 3] = v.w;
            }
        }

        float ov[4][16];
        float l[4] = {0.f, 0.f, 0.f, 0.f};
#pragma unroll
        for (int qi = 0; qi < 4; qi++)
#pragma unroll
            for (int d = 0; d < 16; d++) ov[qi][d] = 0.f;

        for (int j = 0; j < c; j++) {
            const float4* kr = (const float4*)(Ksh + j * HDIM + d0);
            float4 k0 = kr[0], k1 = kr[1], k2 = kr[2], k3 = kr[3];
            float kc[16] = {k0.x, k0.y, k0.z, k0.w, k1.x, k1.y, k1.z, k1.w,
                            k2.x, k2.y, k2.z, k2.w, k3.x, k3.y, k3.z, k3.w};
            float s[4];
#pragma unroll
            for (int qi = 0; qi < 4; qi++) {
                float a = 0.f, b = 0.f;
#pragma unroll
                for (int d = 0; d < 16; d += 2) {
                    a += qreg[qi][d] * kc[d];
                    b += qreg[qi][d + 1] * kc[d + 1];
                }
                s[qi] = a + b;
            }
#pragma unroll
            for (int qi = 0; qi < 4; qi++)
                s[qi] += __shfl_xor_sync(0xffffffffu, s[qi], 1);
#pragma unroll
            for (int qi = 0; qi < 4; qi++)
                s[qi] += __shfl_xor_sync(0xffffffffu, s[qi], 2);

            const float4* vr = (const float4*)(Vsh + j * HDIM + d0);
            float4 v0 = vr[0], v1 = vr[1], v2 = vr[2], v3 = vr[3];
            float vc[16] = {v0.x, v0.y, v0.z, v0.w, v1.x, v1.y, v1.z, v1.w,
                            v2.x, v2.y, v2.z, v2.w, v3.x, v3.y, v3.z, v3.w};
#pragma unroll
            for (int qi = 0; qi < 4; qi++) {
                float p = __expf(fminf(s[qi] * scale, 80.f));
                l[qi] += p;
#pragma unroll
                for (int d = 0; d < 16; d++) ov[qi][d] += p * vc[d];
            }
        }

#pragma unroll
        for (int qi = 0; qi < 4; qi++) {
            if (q0 + qi < c) {
                float inv = 1.f / l[qi];
                size_t row = (size_t)(st + q0 + qi) * KE;
                __half2* dh = (__half2*)(Xe + row + h * HDIM + d0);
                __half2* dl = (__half2*)(Xe + row + 512 + h * HDIM + d0);
                __half2* dh2 = (__half2*)(Xe + row + 1024 + h * HDIM + d0);
#pragma unroll
                for (int t = 0; t < 8; t++) {
                    float a = ov[qi][2 * t] * inv;
                    float b = ov[qi][2 * t + 1] * inv;
                    __half ha = __float2half(a), hb = __float2half(b);
                    __half la = __float2half(a - __half2float(ha));
                    __half lb = __float2half(b - __half2float(hb));
                    __half2 hh = __halves2half2(ha, hb);
                    dh[t] = hh;
                    dl[t] = __halves2half2(la, lb);
                    dh2[t] = hh;
                }
            }
        }
    }
}

// ---------------------------------------------------------------------------
extern "C" void kernel_launch(void* const* d_in, const int* in_sizes, int n_in,
                              void* d_out, int out_size) {
    const float* x  = (const float*)d_in[0];
    const void*  bt = d_in[1];
    const float* wq = (const float*)d_in[2];
    const float* bq = (const float*)d_in[3];
    const float* wk = (const float*)d_in[4];
    const float* bk = (const float*)d_in[5];
    const float* wv = (const float*)d_in[6];
    const float* bv = (const float*)d_in[7];
    const float* wo = (const float*)d_in[8];
    const float* bo = (const float*)d_in[9];
    float* out = (float*)d_out;

    float *QKV, *bcat;
    __half *Xe, *We;
    cudaGetSymbolAddress((void**)&QKV, g_QKV);
    cudaGetSymbolAddress((void**)&Xe, g_Xe);
    cudaGetSymbolAddress((void**)&We, g_We);
    cudaGetSymbolAddress((void**)&bcat, g_bcat);
    __half* Weo = We + 3 * (size_t)HID * KE;

    cudaFuncSetAttribute(gemm_hmma, cudaFuncAttributeMaxDynamicSharedMemorySize, GEMM_SMEM);
    const int attn_smem = 2 * MAXC * HDIM * (int)sizeof(float);  // 192 KB
    cudaFuncSetAttribute(attn_kernel, cudaFuncAttributeMaxDynamicSharedMemorySize, attn_smem);

    starts_kernel<<<(NNODES + 255) / 256, 256>>>(bt, NNODES);
    bias_cat<<<1, HID>>>(bq, bk, bv);

    const int xtot = NNODES * HID;
    expand_a<<<(xtot + 255) / 256, 256>>>(x, Xe, xtot);
    expand_w4<<<(4 * HID * HID + 255) / 256, 256>>>(wq, wk, wv, wo, We);

    // fused Q|K|V projection: N = 1536
    gemm_hmma<<<dim3(12, 80), 256, GEMM_SMEM>>>(Xe, We, bcat, QKV, 3 * HID);

    // attention writes O directly in expanded fp16 form into Xe
    attn_kernel<<<dim3(NGRAPH, HEADS), 256, attn_smem>>>(QKV, Xe);

    // output projection
    gemm_hmma<<<dim3(4, 80), 256, GEMM_SMEM>>>(Xe, Weo, bo, out, HID);
}

// round 7
// speedup vs baseline: 2.0284x; 1.0041x over previous
#include <cuda_runtime.h>
#include <cuda_fp16.h>
#include <cstdint>

#define NNODES 10240
#define NGRAPH 64
#define HID 512
#define HEADS 8
#define HDIM 64
#define MAXC 384

#define KE 1536              // expanded K: A=[hi|lo|hi], B=[hi|hi|lo]
#define KC 64                // halves per K-chunk (128B per row)
#define NKCH (KE / KC)       // 24
#define NSTAGE 3

typedef unsigned long long u64;

// ---------------------------------------------------------------------------
// Scratch (device globals: no allocation allowed)
// ---------------------------------------------------------------------------
__device__ float g_Qf[(size_t)NNODES * HID];                      // Q fp32
__device__ __align__(16) __half g_KVh[(size_t)NNODES * 1024];     // K|V fp16
__device__ __align__(16) __half g_Xe[(size_t)NNODES * KE];        // x / O expanded
__device__ __align__(16) __half g_We[4][(size_t)HID * KE];        // wq,wk,wv,wo expanded
__device__ float g_bcat[3 * HID];
__device__ int g_start[NGRAPH + 2];

// ---------------------------------------------------------------------------
__device__ __forceinline__ uint32_t smem_u32(const void* p) {
    uint32_t a;
    asm("{ .reg .u64 t; cvta.to.shared.u64 t, %1; cvt.u32.u64 %0, t; }" : "=r"(a) : "l"(p));
    return a;
}
__device__ __forceinline__ u64 pack2(float lo, float hi) {
    u64 r; asm("mov.b64 %0, {%1, %2};" : "=l"(r) : "f"(lo), "f"(hi)); return r;
}
__device__ __forceinline__ void unpack2(u64 v, float& lo, float& hi) {
    asm("mov.b64 {%0, %1}, %2;" : "=f"(lo), "=f"(hi) : "l"(v));
}
__device__ __forceinline__ u64 ffma2(u64 a, u64 b, u64 c) {
    u64 d; asm("fma.rn.f32x2 %0, %1, %2, %3;" : "=l"(d) : "l"(a), "l"(b), "l"(c)); return d;
}

// ---------------------------------------------------------------------------
// Segment starts from sorted batch (int32 or int64 storage).
// ---------------------------------------------------------------------------
__global__ void starts_kernel(const void* bptr, int n) {
    const int* b32 = (const int*)bptr;
    const long long* b64 = (const long long*)bptr;
    const bool is64 = (b32[n - 1] == 0);
    int i = blockIdx.x * blockDim.x + threadIdx.x;
    if (i >= n) return;
    int bi = is64 ? (int)b64[i] : b32[i];
    int bp = (i == 0) ? -1 : (is64 ? (int)b64[i - 1] : b32[i - 1]);
    for (int g = bp + 1; g <= bi; ++g) g_start[g] = i;
    if (i == n - 1)
        for (int g = bi + 1; g <= NGRAPH; ++g) g_start[g] = n;
}

__global__ void bias_cat(const float* bq, const float* bk, const float* bv) {
    int i = threadIdx.x;
    g_bcat[i] = bq[i];
    g_bcat[HID + i] = bk[i];
    g_bcat[2 * HID + i] = bv[i];
}

// ---------------------------------------------------------------------------
// fp32 -> fp16 hi/lo expansion.  A layout [hi|lo|hi]; B layout [hi|hi|lo].
// ---------------------------------------------------------------------------
__global__ void expand_a(const float* __restrict__ X, __half* __restrict__ Xe, int total) {
    int i = blockIdx.x * blockDim.x + threadIdx.x;
    if (i >= total) return;
    int r = i >> 9, c = i & 511;
    float v = X[i];
    __half h = __float2half(v);
    __half l = __float2half(v - __half2float(h));
    size_t b = (size_t)r * KE;
    Xe[b + c] = h; Xe[b + 512 + c] = l; Xe[b + 1024 + c] = h;
}

__global__ void expand_w4(const float* __restrict__ w0, const float* __restrict__ w1,
                          const float* __restrict__ w2, const float* __restrict__ w3,
                          __half* __restrict__ We) {
    int i = blockIdx.x * blockDim.x + threadIdx.x;
    if (i >= 4 * HID * HID) return;
    int m = i >> 18;
    int local = i & 262143;
    const float* W = (m == 0) ? w0 : (m == 1) ? w1 : (m == 2) ? w2 : w3;
    int r = local >> 9, c = local & 511;
    float v = W[r * HID + c];
    __half h = __float2half(v);
    __half l = __float2half(v - __half2float(h));
    size_t b = (size_t)m * HID * KE + (size_t)r * KE;
    We[b + c] = h; We[b + 512 + c] = h; We[b + 1024 + c] = l;
}

// ---------------------------------------------------------------------------
// HMMA GEMM: 128 x BN CTA tile, 8 warps (2m x BN/32 n), mma.sync.m16n8k16,
// XOR-swizzled smem, 3-stage cp.async ring.
// SPLIT (QKV): cols < 512 -> Cf fp32 (ld 512); cols >= 512 -> Ch fp16 (ld 1024).
// ---------------------------------------------------------------------------
template <int BN, bool SPLIT>
__global__ __launch_bounds__(256, 2) void gemm_hmma(
    const __half* __restrict__ A, const __half* __restrict__ B,
    const float* __restrict__ bias, float* __restrict__ Cf, __half* __restrict__ Ch)
{
    constexpr int NT = BN / 32;            // n-subtiles per warp
    constexpr int STG_A = 16384;           // 128 rows x 128B
    constexpr int STG_B = BN * 128;
    constexpr int STAGE = STG_A + STG_B;

    extern __shared__ char sm_raw[];
    const int tid = threadIdx.x;
    const int wid = tid >> 5, lane = tid & 31;
    const int bm = blockIdx.y * 128, bn = blockIdx.x * BN;
    const int wm = (wid & 1) * 64;
    const int wn = (wid >> 1) * (BN / 4);
    const uint32_t sbase = smem_u32(sm_raw);

    float acc[4][NT][4];
#pragma unroll
    for (int a = 0; a < 4; a++)
#pragma unroll
        for (int b = 0; b < NT; b++)
#pragma unroll
            for (int c = 0; c < 4; c++) acc[a][b][c] = 0.f;

    const int lr = tid >> 3;
    const int ls = tid & 7;

    auto issue = [&](int ch) {
        const __half* gA = A + (size_t)bm * KE + ch * KC;
        const __half* gB = B + (size_t)bn * KE + ch * KC;
        uint32_t sA = sbase + (ch % NSTAGE) * STAGE;
        uint32_t sB = sA + STG_A;
#pragma unroll
        for (int t = 0; t < 4; t++) {
            int row = lr + t * 32;
            uint32_t off = row * 128 + ((ls ^ (row & 7)) * 16);
            asm volatile("cp.async.cg.shared.global [%0], [%1], 16;"
                         :: "r"(sA + off), "l"(gA + (size_t)row * KE + ls * 8));
        }
#pragma unroll
        for (int t = 0; t < BN / 32; t++) {
            int row = lr + t * 32;
            uint32_t off = row * 128 + ((ls ^ (row & 7)) * 16);
            asm volatile("cp.async.cg.shared.global [%0], [%1], 16;"
                         :: "r"(sB + off), "l"(gB + (size_t)row * KE + ls * 8));
        }
        asm volatile("cp.async.commit_group;");
    };

    issue(0);
    issue(1);

    const int lrow = lane & 15;
    const int lseg = lane >> 4;

    for (int ch = 0; ch < NKCH; ++ch) {
        if (ch < NKCH - 1) asm volatile("cp.async.wait_group 1;");
        else               asm volatile("cp.async.wait_group 0;");
        __syncthreads();
        if (ch + 2 < NKCH) issue(ch + 2);

        const uint32_t sA = sbase + (ch % NSTAGE) * STAGE;
        const uint32_t sB = sA + STG_A;

#pragma unroll
        for (int k = 0; k < KC; k += 16) {
            const int seg = (k >> 3) + lseg;
            uint32_t ar[4][4];
#pragma unroll
            for (int mt = 0; mt < 4; mt++) {
                int row = wm + mt * 16 + lrow;
                uint32_t addr = sA + row * 128 + ((seg ^ (row & 7)) * 16);
                asm volatile("ldmatrix.sync.aligned.m8n8.x4.shared.b16 {%0,%1,%2,%3}, [%4];"
                             : "=r"(ar[mt][0]), "=r"(ar[mt][1]), "=r"(ar[mt][2]), "=r"(ar[mt][3])
                             : "r"(addr));
            }
            uint32_t br[NT / 2][4];
#pragma unroll
            for (int nt2 = 0; nt2 < NT / 2; nt2++) {
                int row = wn + nt2 * 16 + lrow;
                uint32_t addr = sB + row * 128 + ((seg ^ (row & 7)) * 16);
                asm volatile("ldmatrix.sync.aligned.m8n8.x4.shared.b16 {%0,%1,%2,%3}, [%4];"
                             : "=r"(br[nt2][0]), "=r"(br[nt2][1]), "=r"(br[nt2][2]), "=r"(br[nt2][3])
                             : "r"(addr));
            }
#pragma unroll
            for (int mt = 0; mt < 4; mt++)
#pragma unroll
                for (int nt = 0; nt < NT; nt++) {
                    uint32_t b0 = br[nt >> 1][nt & 1];
                    uint32_t b1 = br[nt >> 1][(nt & 1) + 2];
                    asm volatile(
                        "mma.sync.aligned.m16n8k16.row.col.f32.f16.f16.f32 "
                        "{%0,%1,%2,%3}, {%4,%5,%6,%7}, {%8,%9}, {%0,%1,%2,%3};"
                        : "+f"(acc[mt][nt][0]), "+f"(acc[mt][nt][1]),
                          "+f"(acc[mt][nt][2]), "+f"(acc[mt][nt][3])
                        : "r"(ar[mt][0]), "r"(ar[mt][1]), "r"(ar[mt][2]), "r"(ar[mt][3]),
                          "r"(b0), "r"(b1));
                }
        }
        __syncthreads();
    }

    const int r0 = bm + wm + (lane >> 2);
    const int c0 = bn + wn + (lane & 3) * 2;
#pragma unroll
    for (int nt = 0; nt < NT; nt++) {
        int col = c0 + nt * 8;
        float2 bb = *(const float2*)(bias + col);
#pragma unroll
        for (int mt = 0; mt < 4; mt++) {
            int row = r0 + mt * 16;
            float2 v0 = make_float2(acc[mt][nt][0] + bb.x, acc[mt][nt][1] + bb.y);
            float2 v1 = make_float2(acc[mt][nt][2] + bb.x, acc[mt][nt][3] + bb.y);
            if (SPLIT && bn >= 512) {
                int ch_col = col - 512;
                *(__half2*)(Ch + (size_t)row * 1024 + ch_col) = __floats2half2_rn(v0.x, v0.y);
                *(__half2*)(Ch + (size_t)(row + 8) * 1024 + ch_col) = __floats2half2_rn(v1.x, v1.y);
            } else {
                *(float2*)(Cf + (size_t)row * 512 + col) = v0;
                *(float2*)(Cf + (size_t)(row + 8) * 512 + col) = v1;
            }
        }
    }
}

// ---------------------------------------------------------------------------
// Attention: one block per (graph, head). K,V fp16 in smem (96 KB, 2 CTAs/SM).
// 8 lanes per query-group, 4 queries/group; lane owns 8 of 64 dims.
// Packed f32x2 FMA for dots and V accumulation; butterfly shfl reduce;
// single-pass softmax (no max subtraction; logits small).
// Output written in fp16 [hi|lo|hi] expanded layout into g_Xe.
// ---------------------------------------------------------------------------
__global__ __launch_bounds__(256, 2) void attn_kernel(
    const float* __restrict__ Qf, const __half* __restrict__ KVh,
    __half* __restrict__ Xe)
{
    extern __shared__ __half smh[];
    __half* Ksh = smh;                  // [c][64]
    __half* Vsh = smh + MAXC * HDIM;
    const int g = blockIdx.x;
    const int h = blockIdx.y;
    const int st = g_start[g];
    const int c = g_start[g + 1] - st;
    if (c <= 0) return;
    const int tid = threadIdx.x;

    for (int idx = tid; idx < c * 8; idx += 256) {
        int r = idx >> 3;
        int u = (idx & 7) * 8;
        const __half* src = KVh + (size_t)(st + r) * 1024 + h * HDIM + u;
        *(uint4*)(Ksh + r * HDIM + u) = *(const uint4*)src;
        *(uint4*)(Vsh + r * HDIM + u) = *(const uint4*)(src + 512);
    }
    __syncthreads();

    const int grp = tid >> 3;        // 0..31
    const int d0 = (tid & 7) * 8;    // dim slice
    const float scale = 0.125f;

    for (int qb = 0; qb < c; qb += 128) {
        const int q0 = qb + grp * 4;

        u64 qreg[4][4];
#pragma unroll
        for (int qi = 0; qi < 4; qi++) {
            int qq = min(q0 + qi, c - 1);
            const float4* qp = (const float4*)(Qf + (size_t)(st + qq) * 512 + h * HDIM + d0);
            float4 a = qp[0], b = qp[1];
            qreg[qi][0] = pack2(a.x, a.y); qreg[qi][1] = pack2(a.z, a.w);
            qreg[qi][2] = pack2(b.x, b.y); qreg[qi][3] = pack2(b.z, b.w);
        }

        u64 ov[4][4];
        float l[4] = {0.f, 0.f, 0.f, 0.f};
#pragma unroll
        for (int qi = 0; qi < 4; qi++)
#pragma unroll
            for (int t = 0; t < 4; t++) ov[qi][t] = 0ull;

        for (int j = 0; j < c; j++) {
            uint4 kraw = *(const uint4*)(Ksh + j * HDIM + d0);
            const __half2* kh = (const __half2*)&kraw;
            u64 kc[4];
#pragma unroll
            for (int t = 0; t < 4; t++) {
                float2 f = __half22float2(kh[t]);
                kc[t] = pack2(f.x, f.y);
            }
            float s[4];
#pragma unroll
            for (int qi = 0; qi < 4; qi++) {
                u64 s2 = ffma2(qreg[qi][0], kc[0],
                         ffma2(qreg[qi][1], kc[1],
                         ffma2(qreg[qi][2], kc[2],
                         ffma2(qreg[qi][3], kc[3], 0ull))));
                float lo, hi; unpack2(s2, lo, hi);
                s[qi] = lo + hi;
            }
#pragma unroll
            for (int qi = 0; qi < 4; qi++)
                s[qi] += __shfl_xor_sync(0xffffffffu, s[qi], 1);
#pragma unroll
            for (int qi = 0; qi < 4; qi++)
                s[qi] += __shfl_xor_sync(0xffffffffu, s[qi], 2);
#pragma unroll
            for (int qi = 0; qi < 4; qi++)
                s[qi] += __shfl_xor_sync(0xffffffffu, s[qi], 4);

            uint4 vraw = *(const uint4*)(Vsh + j * HDIM + d0);
            const __half2* vh = (const __half2*)&vraw;
            u64 vc[4];
#pragma unroll
            for (int t = 0; t < 4; t++) {
                float2 f = __half22float2(vh[t]);
                vc[t] = pack2(f.x, f.y);
            }
#pragma unroll
            for (int qi = 0; qi < 4; qi++) {
                float p = __expf(fminf(s[qi] * scale, 80.f));
                l[qi] += p;
                u64 p2 = pack2(p, p);
#pragma unroll
                for (int t = 0; t < 4; t++) ov[qi][t] = ffma2(p2, vc[t], ov[qi][t]);
            }
        }

#pragma unroll
        for (int qi = 0; qi < 4; qi++) {
            if (q0 + qi < c) {
                float inv = 1.f / l[qi];
                size_t row = (size_t)(st + q0 + qi) * KE;
                __half2* dh = (__half2*)(Xe + row + h * HDIM + d0);
                __half2* dl = (__half2*)(Xe + row + 512 + h * HDIM + d0);
                __half2* dh2 = (__half2*)(Xe + row + 1024 + h * HDIM + d0);
#pragma unroll
                for (int t = 0; t < 4; t++) {
                    float a, b; unpack2(ov[qi][t], a, b);
                    a *= inv; b *= inv;
                    __half ha = __float2half(a), hb = __float2half(b);
                    __half la = __float2half(a - __half2float(ha));
                    __half lb = __float2half(b - __half2float(hb));
                    __half2 hh = __halves2half2(ha, hb);
                    dh[t] = hh;
                    dl[t] = __halves2half2(la, lb);
                    dh2[t] = hh;
                }
            }
        }
    }
}

// ---------------------------------------------------------------------------
extern "C" void kernel_launch(void* const* d_in, const int* in_sizes, int n_in,
                              void* d_out, int out_size) {
    const float* x  = (const float*)d_in[0];
    const void*  bt = d_in[1];
    const float* wq = (const float*)d_in[2];
    const float* bq = (const float*)d_in[3];
    const float* wk = (const float*)d_in[4];
    const float* bk = (const float*)d_in[5];
    const float* wv = (const float*)d_in[6];
    const float* bv = (const float*)d_in[7];
    const float* wo = (const float*)d_in[8];
    const float* bo = (const float*)d_in[9];
    float* out = (float*)d_out;

    float *Qf, *bcat;
    __half *KVh, *Xe, *We;
    cudaGetSymbolAddress((void**)&Qf, g_Qf);
    cudaGetSymbolAddress((void**)&KVh, g_KVh);
    cudaGetSymbolAddress((void**)&Xe, g_Xe);
    cudaGetSymbolAddress((void**)&We, g_We);
    cudaGetSymbolAddress((void**)&bcat, g_bcat);
    __half* Weo = We + 3 * (size_t)HID * KE;

    const int smem128 = NSTAGE * (16384 + 128 * 128);  // 98304
    const int smem64  = NSTAGE * (16384 + 64 * 128);   // 73728
    cudaFuncSetAttribute(gemm_hmma<128, true>,
                         cudaFuncAttributeMaxDynamicSharedMemorySize, smem128);
    cudaFuncSetAttribute(gemm_hmma<64, false>,
                         cudaFuncAttributeMaxDynamicSharedMemorySize, smem64);
    const int attn_smem = 2 * MAXC * HDIM * (int)sizeof(__half);  // 96 KB
    cudaFuncSetAttribute(attn_kernel, cudaFuncAttributeMaxDynamicSharedMemorySize, attn_smem);

    starts_kernel<<<(NNODES + 255) / 256, 256>>>(bt, NNODES);
    bias_cat<<<1, HID>>>(bq, bk, bv);

    const int xtot = NNODES * HID;
    expand_a<<<(xtot + 255) / 256, 256>>>(x, Xe, xtot);
    expand_w4<<<(4 * HID * HID + 255) / 256, 256>>>(wq, wk, wv, wo, We);

    // fused Q|K|V projection: N = 1536 (Q -> fp32, K|V -> fp16)
    gemm_hmma<128, true><<<dim3(12, 80), 256, smem128>>>(Xe, We, bcat, Qf, KVh);

    // attention writes O directly in expanded fp16 form into Xe
    attn_kernel<<<dim3(NGRAPH, HEADS), 256, attn_smem>>>(Qf, KVh, Xe);

    // output projection: 128x64 tiles -> 640 CTAs (reduced tail waste)
    gemm_hmma<64, false><<<dim3(8, 80), 256, smem64>>>(Xe, Weo, bo, out, nullptr);
}

// round 8
// speedup vs baseline: 3.6071x; 1.7783x over previous
#include <cuda_runtime.h>
#include <cuda_fp16.h>
#include <cstdint>

#define NNODES 10240
#define NGRAPH 64
#define HID 512
#define HEADS 8
#define HDIM 64
#define MAXC 384

#define KE 1536              // expanded K: A=[hi|lo|hi], B=[hi|hi|lo]
#define KC 64                // halves per K-chunk (128B per row)
#define NKCH (KE / KC)       // 24
#define NSTAGE 3

typedef unsigned long long u64;

// ---------------------------------------------------------------------------
// Scratch (device globals: no allocation allowed)
// ---------------------------------------------------------------------------
__device__ float g_Qf[(size_t)NNODES * HID];                      // Q fp32
__device__ __align__(16) __half g_KVh[(size_t)NNODES * 1024];     // K|V fp16
__device__ __align__(16) __half g_Xe[(size_t)NNODES * KE];        // x / O expanded
__device__ __align__(16) __half g_We[4][(size_t)HID * KE];        // wq,wk,wv,wo expanded
__device__ float g_bcat[3 * HID];
__device__ int g_start[NGRAPH + 2];

// ---------------------------------------------------------------------------
__device__ __forceinline__ uint32_t smem_u32(const void* p) {
    uint32_t a;
    asm("{ .reg .u64 t; cvta.to.shared.u64 t, %1; cvt.u32.u64 %0, t; }" : "=r"(a) : "l"(p));
    return a;
}

// ---------------------------------------------------------------------------
// Segment starts from sorted batch (int32 or int64 storage).
// ---------------------------------------------------------------------------
__global__ void starts_kernel(const void* bptr, int n) {
    const int* b32 = (const int*)bptr;
    const long long* b64 = (const long long*)bptr;
    const bool is64 = (b32[n - 1] == 0);
    int i = blockIdx.x * blockDim.x + threadIdx.x;
    if (i >= n) return;
    int bi = is64 ? (int)b64[i] : b32[i];
    int bp = (i == 0) ? -1 : (is64 ? (int)b64[i - 1] : b32[i - 1]);
    for (int g = bp + 1; g <= bi; ++g) g_start[g] = i;
    if (i == n - 1)
        for (int g = bi + 1; g <= NGRAPH; ++g) g_start[g] = n;
}

__global__ void bias_cat(const float* bq, const float* bk, const float* bv) {
    int i = threadIdx.x;
    g_bcat[i] = bq[i];
    g_bcat[HID + i] = bk[i];
    g_bcat[2 * HID + i] = bv[i];
}

// ---------------------------------------------------------------------------
// fp32 -> fp16 hi/lo expansion.  A layout [hi|lo|hi]; B layout [hi|hi|lo].
// ---------------------------------------------------------------------------
__global__ void expand_a(const float* __restrict__ X, __half* __restrict__ Xe, int total) {
    int i = blockIdx.x * blockDim.x + threadIdx.x;
    if (i >= total) return;
    int r = i >> 9, c = i & 511;
    float v = X[i];
    __half h = __float2half(v);
    __half l = __float2half(v - __half2float(h));
    size_t b = (size_t)r * KE;
    Xe[b + c] = h; Xe[b + 512 + c] = l; Xe[b + 1024 + c] = h;
}

__global__ void expand_w4(const float* __restrict__ w0, const float* __restrict__ w1,
                          const float* __restrict__ w2, const float* __restrict__ w3,
                          __half* __restrict__ We) {
    int i = blockIdx.x * blockDim.x + threadIdx.x;
    if (i >= 4 * HID * HID) return;
    int m = i >> 18;
    int local = i & 262143;
    const float* W = (m == 0) ? w0 : (m == 1) ? w1 : (m == 2) ? w2 : w3;
    int r = local >> 9, c = local & 511;
    float v = W[r * HID + c];
    __half h = __float2half(v);
    __half l = __float2half(v - __half2float(h));
    size_t b = (size_t)m * HID * KE + (size_t)r * KE;
    We[b + c] = h; We[b + 512 + c] = h; We[b + 1024 + c] = l;
}

// ---------------------------------------------------------------------------
// HMMA GEMM (unchanged from R7, passing): 128 x BN CTA tile, 8 warps,
// mma.sync.m16n8k16, XOR-swizzled smem, 3-stage cp.async ring.
// SPLIT (QKV): cols < 512 -> Cf fp32; cols >= 512 -> Ch fp16 (ld 1024).
// ---------------------------------------------------------------------------
template <int BN, bool SPLIT>
__global__ __launch_bounds__(256, 2) void gemm_hmma(
    const __half* __restrict__ A, const __half* __restrict__ B,
    const float* __restrict__ bias, float* __restrict__ Cf, __half* __restrict__ Ch)
{
    constexpr int NT = BN / 32;
    constexpr int STG_A = 16384;
    constexpr int STG_B = BN * 128;
    constexpr int STAGE = STG_A + STG_B;

    extern __shared__ char sm_raw[];
    const int tid = threadIdx.x;
    const int wid = tid >> 5, lane = tid & 31;
    const int bm = blockIdx.y * 128, bn = blockIdx.x * BN;
    const int wm = (wid & 1) * 64;
    const int wn = (wid >> 1) * (BN / 4);
    const uint32_t sbase = smem_u32(sm_raw);

    float acc[4][NT][4];
#pragma unroll
    for (int a = 0; a < 4; a++)
#pragma unroll
        for (int b = 0; b < NT; b++)
#pragma unroll
            for (int c = 0; c < 4; c++) acc[a][b][c] = 0.f;

    const int lr = tid >> 3;
    const int ls = tid & 7;

    auto issue = [&](int ch) {
        const __half* gA = A + (size_t)bm * KE + ch * KC;
        const __half* gB = B + (size_t)bn * KE + ch * KC;
        uint32_t sA = sbase + (ch % NSTAGE) * STAGE;
        uint32_t sB = sA + STG_A;
#pragma unroll
        for (int t = 0; t < 4; t++) {
            int row = lr + t * 32;
            uint32_t off = row * 128 + ((ls ^ (row & 7)) * 16);
            asm volatile("cp.async.cg.shared.global [%0], [%1], 16;"
                         :: "r"(sA + off), "l"(gA + (size_t)row * KE + ls * 8));
        }
#pragma unroll
        for (int t = 0; t < BN / 32; t++) {
            int row = lr + t * 32;
            uint32_t off = row * 128 + ((ls ^ (row & 7)) * 16);
            asm volatile("cp.async.cg.shared.global [%0], [%1], 16;"
                         :: "r"(sB + off), "l"(gB + (size_t)row * KE + ls * 8));
        }
        asm volatile("cp.async.commit_group;");
    };

    issue(0);
    issue(1);

    const int lrow = lane & 15;
    const int lseg = lane >> 4;

    for (int ch = 0; ch < NKCH; ++ch) {
        if (ch < NKCH - 1) asm volatile("cp.async.wait_group 1;");
        else               asm volatile("cp.async.wait_group 0;");
        __syncthreads();
        if (ch + 2 < NKCH) issue(ch + 2);

        const uint32_t sA = sbase + (ch % NSTAGE) * STAGE;
        const uint32_t sB = sA + STG_A;

#pragma unroll
        for (int k = 0; k < KC; k += 16) {
            const int seg = (k >> 3) + lseg;
            uint32_t ar[4][4];
#pragma unroll
            for (int mt = 0; mt < 4; mt++) {
                int row = wm + mt * 16 + lrow;
                uint32_t addr = sA + row * 128 + ((seg ^ (row & 7)) * 16);
                asm volatile("ldmatrix.sync.aligned.m8n8.x4.shared.b16 {%0,%1,%2,%3}, [%4];"
                             : "=r"(ar[mt][0]), "=r"(ar[mt][1]), "=r"(ar[mt][2]), "=r"(ar[mt][3])
                             : "r"(addr));
            }
            uint32_t br[NT / 2][4];
#pragma unroll
            for (int nt2 = 0; nt2 < NT / 2; nt2++) {
                int row = wn + nt2 * 16 + lrow;
                uint32_t addr = sB + row * 128 + ((seg ^ (row & 7)) * 16);
                asm volatile("ldmatrix.sync.aligned.m8n8.x4.shared.b16 {%0,%1,%2,%3}, [%4];"
                             : "=r"(br[nt2][0]), "=r"(br[nt2][1]), "=r"(br[nt2][2]), "=r"(br[nt2][3])
                             : "r"(addr));
            }
#pragma unroll
            for (int mt = 0; mt < 4; mt++)
#pragma unroll
                for (int nt = 0; nt < NT; nt++) {
                    uint32_t b0 = br[nt >> 1][nt & 1];
                    uint32_t b1 = br[nt >> 1][(nt & 1) + 2];
                    asm volatile(
                        "mma.sync.aligned.m16n8k16.row.col.f32.f16.f16.f32 "
                        "{%0,%1,%2,%3}, {%4,%5,%6,%7}, {%8,%9}, {%0,%1,%2,%3};"
                        : "+f"(acc[mt][nt][0]), "+f"(acc[mt][nt][1]),
                          "+f"(acc[mt][nt][2]), "+f"(acc[mt][nt][3])
                        : "r"(ar[mt][0]), "r"(ar[mt][1]), "r"(ar[mt][2]), "r"(ar[mt][3]),
                          "r"(b0), "r"(b1));
                }
        }
        __syncthreads();
    }

    const int r0 = bm + wm + (lane >> 2);
    const int c0 = bn + wn + (lane & 3) * 2;
#pragma unroll
    for (int nt = 0; nt < NT; nt++) {
        int col = c0 + nt * 8;
        float2 bb = *(const float2*)(bias + col);
#pragma unroll
        for (int mt = 0; mt < 4; mt++) {
            int row = r0 + mt * 16;
            float2 v0 = make_float2(acc[mt][nt][0] + bb.x, acc[mt][nt][1] + bb.y);
            float2 v1 = make_float2(acc[mt][nt][2] + bb.x, acc[mt][nt][3] + bb.y);
            if (SPLIT && bn >= 512) {
                int ch_col = col - 512;
                *(__half2*)(Ch + (size_t)row * 1024 + ch_col) = __floats2half2_rn(v0.x, v0.y);
                *(__half2*)(Ch + (size_t)(row + 8) * 1024 + ch_col) = __floats2half2_rn(v1.x, v1.y);
            } else {
                *(float2*)(Cf + (size_t)row * 512 + col) = v0;
                *(float2*)(Cf + (size_t)(row + 8) * 512 + col) = v1;
            }
        }
    }
}

// ---------------------------------------------------------------------------
// Tensor-core attention. One block per (graph, head); 8 warps.
// K,V fp16 XOR-swizzled in smem (pad rows zeroed to multiple of 16).
// Each warp: 16-query tile. S = Q K^T via mma (K b-frag non-trans),
// p = exp(s/8) fp32 -> fp16 a-frag, O = P V via mma (V b-frag via
// ldmatrix.trans). Softmax denom: sum of fp16-rounded p minus npad
// (pad keys give p == 1 exactly since K_pad = 0). Output -> Xe [hi|lo|hi].
// ---------------------------------------------------------------------------
#define ATTN_SMEM (2 * MAXC * 128 + 8 * 2048)   // K 48K + V 48K + Q 16K = 112K

__device__ __forceinline__ void store_expanded(__half* Xe, int node, int col,
                                               float a, float b) {
    size_t row = (size_t)node * KE;
    __half ha = __float2half(a), hb = __float2half(b);
    __half la = __float2half(a - __half2float(ha));
    __half lb = __float2half(b - __half2float(hb));
    __half2 hh = __halves2half2(ha, hb);
    *(__half2*)(Xe + row + col) = hh;
    *(__half2*)(Xe + row + 512 + col) = __halves2half2(la, lb);
    *(__half2*)(Xe + row + 1024 + col) = hh;
}

__global__ __launch_bounds__(256, 2) void attn_tc(
    const float* __restrict__ Qf, const __half* __restrict__ KVh,
    __half* __restrict__ Xe)
{
    extern __shared__ __align__(16) char smraw[];
    char* Kc = smraw;                     // [MAXC][128B]
    char* Vc = smraw + MAXC * 128;
    char* Qc = smraw + 2 * MAXC * 128;    // 8 warps x 2048B
    const uint32_t sK = smem_u32(Kc);
    const uint32_t sV = smem_u32(Vc);
    const uint32_t sQ = smem_u32(Qc);

    const int g = blockIdx.x, h = blockIdx.y;
    const int st = g_start[g];
    const int c = g_start[g + 1] - st;
    if (c <= 0) return;
    const int c16 = (c + 15) & ~15;
    const int nkt = c16 >> 4;
    const float fnpad = (float)(c16 - c);
    const int tid = threadIdx.x, wid = tid >> 5, lane = tid & 31;

    // stage K,V (fp16, swizzled); zero pad rows
    for (int idx = tid; idx < c16 * 8; idx += 256) {
        int r = idx >> 3, u = idx & 7;
        uint32_t off = r * 128 + ((u ^ (r & 7)) * 16);
        uint4 kv = make_uint4(0, 0, 0, 0), vv = make_uint4(0, 0, 0, 0);
        if (r < c) {
            const __half* src = KVh + (size_t)(st + r) * 1024 + h * HDIM + u * 8;
            kv = *(const uint4*)src;
            vv = *(const uint4*)(src + 512);
        }
        *(uint4*)(Kc + off) = kv;
        *(uint4*)(Vc + off) = vv;
    }
    __syncthreads();

    const int lrow = lane & 15;
    const int lseg = lane >> 4;
    const int ntiles = (c + 15) >> 4;
    const uint32_t qb32 = sQ + wid * 2048;
    char* qbc = Qc + wid * 2048;
    const float scale = 0.125f;

    for (int qt = wid; qt < ntiles; qt += 8) {
        // stage this warp's 16x64 Q tile, fp32 -> fp16, swizzled
        for (int t = lane; t < 128; t += 32) {
            int row = t & 15, seg = t >> 4;
            int qrow = qt * 16 + row;
            if (qrow >= c) qrow = c - 1;
            const float4* qp = (const float4*)(Qf + (size_t)(st + qrow) * 512 + h * HDIM + seg * 8);
            float4 x0 = qp[0], x1 = qp[1];
            __half2 h0 = __floats2half2_rn(x0.x, x0.y);
            __half2 h1 = __floats2half2_rn(x0.z, x0.w);
            __half2 h2 = __floats2half2_rn(x1.x, x1.y);
            __half2 h3 = __floats2half2_rn(x1.z, x1.w);
            uint4 pk;
            pk.x = *(uint32_t*)&h0; pk.y = *(uint32_t*)&h1;
            pk.z = *(uint32_t*)&h2; pk.w = *(uint32_t*)&h3;
            *(uint4*)(qbc + row * 128 + ((seg ^ (row & 7)) * 16)) = pk;
        }
        __syncwarp();

        // Q a-frags: aq[kstep][0..3]
        uint32_t aq[4][4];
#pragma unroll
        for (int ks = 0; ks < 4; ks++) {
            uint32_t addr = qb32 + lrow * 128 + (((ks * 2 + lseg) ^ (lrow & 7)) * 16);
            asm volatile("ldmatrix.sync.aligned.m8n8.x4.shared.b16 {%0,%1,%2,%3}, [%4];"
                         : "=r"(aq[ks][0]), "=r"(aq[ks][1]), "=r"(aq[ks][2]), "=r"(aq[ks][3])
                         : "r"(addr));
        }

        float oacc[8][4];
#pragma unroll
        for (int d = 0; d < 8; d++)
#pragma unroll
            for (int e = 0; e < 4; e++) oacc[d][e] = 0.f;
        float lr = 0.f, lr8 = 0.f;

        for (int kt = 0; kt < nkt; kt++) {
            const int krow = kt * 16 + lrow;
            // S = Q K^T  (2 n-tiles of 8 keys)
            float sacc[2][4];
#pragma unroll
            for (int nt = 0; nt < 2; nt++)
#pragma unroll
                for (int e = 0; e < 4; e++) sacc[nt][e] = 0.f;
#pragma unroll
            for (int ks = 0; ks < 4; ks++) {
                uint32_t addr = sK + krow * 128 + (((ks * 2 + lseg) ^ (krow & 7)) * 16);
                uint32_t bk[4];
                asm volatile("ldmatrix.sync.aligned.m8n8.x4.shared.b16 {%0,%1,%2,%3}, [%4];"
                             : "=r"(bk[0]), "=r"(bk[1]), "=r"(bk[2]), "=r"(bk[3])
                             : "r"(addr));
#pragma unroll
                for (int nt = 0; nt < 2; nt++) {
                    asm volatile(
                        "mma.sync.aligned.m16n8k16.row.col.f32.f16.f16.f32 "
                        "{%0,%1,%2,%3}, {%4,%5,%6,%7}, {%8,%9}, {%0,%1,%2,%3};"
                        : "+f"(sacc[nt][0]), "+f"(sacc[nt][1]),
                          "+f"(sacc[nt][2]), "+f"(sacc[nt][3])
                        : "r"(aq[ks][0]), "r"(aq[ks][1]), "r"(aq[ks][2]), "r"(aq[ks][3]),
                          "r"(bk[nt]), "r"(bk[nt + 2]));
                }
            }
            // p = exp(s*scale); pack to fp16 a-frag; accumulate denom from
            // the fp16-rounded values (cancels num/denom rounding).
            float p00 = __expf(fminf(sacc[0][0] * scale, 10.f));
            float p01 = __expf(fminf(sacc[0][1] * scale, 10.f));
            float p02 = __expf(fminf(sacc[0][2] * scale, 10.f));
            float p03 = __expf(fminf(sacc[0][3] * scale, 10.f));
            float p10 = __expf(fminf(sacc[1][0] * scale, 10.f));
            float p11 = __expf(fminf(sacc[1][1] * scale, 10.f));
            float p12 = __expf(fminf(sacc[1][2] * scale, 10.f));
            float p13 = __expf(fminf(sacc[1][3] * scale, 10.f));
            __half2 a0 = __floats2half2_rn(p00, p01);
            __half2 a1 = __floats2half2_rn(p02, p03);
            __half2 a2 = __floats2half2_rn(p10, p11);
            __half2 a3 = __floats2half2_rn(p12, p13);
            float2 f;
            f = __half22float2(a0); lr += f.x + f.y;
            f = __half22float2(a1); lr8 += f.x + f.y;
            f = __half22float2(a2); lr += f.x + f.y;
            f = __half22float2(a3); lr8 += f.x + f.y;
            uint32_t pa0 = *(uint32_t*)&a0, pa1 = *(uint32_t*)&a1;
            uint32_t pa2 = *(uint32_t*)&a2, pa3 = *(uint32_t*)&a3;

            // O += P V  (V b-frags via ldmatrix.trans; 4 x 16-dim blocks)
#pragma unroll
            for (int v16 = 0; v16 < 4; v16++) {
                uint32_t addr = sV + krow * 128 + (((v16 * 2 + lseg) ^ (krow & 7)) * 16);
                uint32_t bv[4];
                asm volatile("ldmatrix.sync.aligned.m8n8.x4.trans.shared.b16 {%0,%1,%2,%3}, [%4];"
                             : "=r"(bv[0]), "=r"(bv[1]), "=r"(bv[2]), "=r"(bv[3])
                             : "r"(addr));
                asm volatile(
                    "mma.sync.aligned.m16n8k16.row.col.f32.f16.f16.f32 "
                    "{%0,%1,%2,%3}, {%4,%5,%6,%7}, {%8,%9}, {%0,%1,%2,%3};"
                    : "+f"(oacc[v16 * 2][0]), "+f"(oacc[v16 * 2][1]),
                      "+f"(oacc[v16 * 2][2]), "+f"(oacc[v16 * 2][3])
                    : "r"(pa0), "r"(pa1), "r"(pa2), "r"(pa3),
                      "r"(bv[0]), "r"(bv[1]));
                asm volatile(
                    "mma.sync.aligned.m16n8k16.row.col.f32.f16.f16.f32 "
                    "{%0,%1,%2,%3}, {%4,%5,%6,%7}, {%8,%9}, {%0,%1,%2,%3};"
                    : "+f"(oacc[v16 * 2 + 1][0]), "+f"(oacc[v16 * 2 + 1][1]),
                      "+f"(oacc[v16 * 2 + 1][2]), "+f"(oacc[v16 * 2 + 1][3])
                    : "r"(pa0), "r"(pa1), "r"(pa2), "r"(pa3),
                      "r"(bv[2]), "r"(bv[3]));
            }
        }

        // reduce softmax denominators over the 4 lanes sharing a row
        lr += __shfl_xor_sync(0xffffffffu, lr, 1);
        lr += __shfl_xor_sync(0xffffffffu, lr, 2);
        lr8 += __shfl_xor_sync(0xffffffffu, lr8, 1);
        lr8 += __shfl_xor_sync(0xffffffffu, lr8, 2);
        float inv = 1.f / (lr - fnpad);
        float inv8 = 1.f / (lr8 - fnpad);

        const int r0 = qt * 16 + (lane >> 2);
#pragma unroll
        for (int dt = 0; dt < 8; dt++) {
            int col = h * HDIM + dt * 8 + (lane & 3) * 2;
            if (r0 < c)
                store_expanded(Xe, st + r0, col, oacc[dt][0] * inv, oacc[dt][1] * inv);
            if (r0 + 8 < c)
                store_expanded(Xe, st + r0 + 8, col, oacc[dt][2] * inv8, oacc[dt][3] * inv8);
        }
    }
}

// ---------------------------------------------------------------------------
extern "C" void kernel_launch(void* const* d_in, const int* in_sizes, int n_in,
                              void* d_out, int out_size) {
    const float* x  = (const float*)d_in[0];
    const void*  bt = d_in[1];
    const float* wq = (const float*)d_in[2];
    const float* bq = (const float*)d_in[3];
    const float* wk = (const float*)d_in[4];
    const float* bk = (const float*)d_in[5];
    const float* wv = (const float*)d_in[6];
    const float* bv = (const float*)d_in[7];
    const float* wo = (const float*)d_in[8];
    const float* bo = (const float*)d_in[9];
    float* out = (float*)d_out;

    float *Qf, *bcat;
    __half *KVh, *Xe, *We;
    cudaGetSymbolAddress((void**)&Qf, g_Qf);
    cudaGetSymbolAddress((void**)&KVh, g_KVh);
    cudaGetSymbolAddress((void**)&Xe, g_Xe);
    cudaGetSymbolAddress((void**)&We, g_We);
    cudaGetSymbolAddress((void**)&bcat, g_bcat);
    __half* Weo = We + 3 * (size_t)HID * KE;

    const int smem128 = NSTAGE * (16384 + 128 * 128);  // 98304
    const int smem64  = NSTAGE * (16384 + 64 * 128);   // 73728
    cudaFuncSetAttribute(gemm_hmma<128, true>,
                         cudaFuncAttributeMaxDynamicSharedMemorySize, smem128);
    cudaFuncSetAttribute(gemm_hmma<64, false>,
                         cudaFuncAttributeMaxDynamicSharedMemorySize, smem64);
    cudaFuncSetAttribute(attn_tc,
                         cudaFuncAttributeMaxDynamicSharedMemorySize, ATTN_SMEM);

    starts_kernel<<<(NNODES + 255) / 256, 256>>>(bt, NNODES);
    bias_cat<<<1, HID>>>(bq, bk, bv);

    const int xtot = NNODES * HID;
    expand_a<<<(xtot + 255) / 256, 256>>>(x, Xe, xtot);
    expand_w4<<<(4 * HID * HID + 255) / 256, 256>>>(wq, wk, wv, wo, We);

    // fused Q|K|V projection: N = 1536 (Q -> fp32, K|V -> fp16)
    gemm_hmma<128, true><<<dim3(12, 80), 256, smem128>>>(Xe, We, bcat, Qf, KVh);

    // tensor-core attention; writes O directly in expanded fp16 form into Xe
    attn_tc<<<dim3(NGRAPH, HEADS), 256, ATTN_SMEM>>>(Qf, KVh, Xe);

    // output projection: 128x64 tiles -> 640 CTAs
    gemm_hmma<64, false><<<dim3(8, 80), 256, smem64>>>(Xe, Weo, bo, out, nullptr);
}

// round 9
// speedup vs baseline: 4.8095x; 1.3333x over previous
#include <cuda_runtime.h>
#include <cuda_fp16.h>
#include <cstdint>

#define NNODES 10240
#define NGRAPH 64
#define HID 512
#define HEADS 8
#define HDIM 64
#define MAXC 384

#define KE 1024              // expanded K: A=[hi|lo], B=[hi|hi] -> C = x * fp16(W)
#define KC 64                // halves per K-chunk (128B per row)
#define NKCH (KE / KC)       // 16
#define NSTAGE 3

typedef unsigned long long u64;

// ---------------------------------------------------------------------------
// Scratch (device globals: no allocation allowed)
// ---------------------------------------------------------------------------
__device__ float g_Qf[(size_t)NNODES * HID];                      // Q fp32
__device__ __align__(16) __half g_KVh[(size_t)NNODES * 1024];     // K|V fp16
__device__ __align__(16) __half g_Xe[(size_t)NNODES * KE];        // x / O expanded [hi|lo]
__device__ __align__(16) __half g_We[4][(size_t)HID * KE];        // wq,wk,wv,wo expanded [hi|hi]
__device__ float g_bcat[3 * HID];
__device__ int g_start[NGRAPH + 2];

// ---------------------------------------------------------------------------
__device__ __forceinline__ uint32_t smem_u32(const void* p) {
    uint32_t a;
    asm("{ .reg .u64 t; cvta.to.shared.u64 t, %1; cvt.u32.u64 %0, t; }" : "=r"(a) : "l"(p));
    return a;
}

// ---------------------------------------------------------------------------
// Segment starts from sorted batch (int32 or int64 storage).
// ---------------------------------------------------------------------------
__global__ void starts_kernel(const void* bptr, int n) {
    const int* b32 = (const int*)bptr;
    const long long* b64 = (const long long*)bptr;
    const bool is64 = (b32[n - 1] == 0);
    int i = blockIdx.x * blockDim.x + threadIdx.x;
    if (i >= n) return;
    int bi = is64 ? (int)b64[i] : b32[i];
    int bp = (i == 0) ? -1 : (is64 ? (int)b64[i - 1] : b32[i - 1]);
    for (int g = bp + 1; g <= bi; ++g) g_start[g] = i;
    if (i == n - 1)
        for (int g = bi + 1; g <= NGRAPH; ++g) g_start[g] = n;
}

__global__ void bias_cat(const float* bq, const float* bk, const float* bv) {
    int i = threadIdx.x;
    g_bcat[i] = bq[i];
    g_bcat[HID + i] = bk[i];
    g_bcat[2 * HID + i] = bv[i];
}

// ---------------------------------------------------------------------------
// fp32 -> fp16 expansion. A side [hi|lo] (exact to 2^-22);
// B side [hi|hi] (W quantized to fp16; dropped term = x*loW ~ 2^-12 RMS).
// ---------------------------------------------------------------------------
__global__ void expand_a(const float* __restrict__ X, __half* __restrict__ Xe, int total) {
    int i = blockIdx.x * blockDim.x + threadIdx.x;
    if (i >= total) return;
    int r = i >> 9, c = i & 511;
    float v = X[i];
    __half h = __float2half(v);
    __half l = __float2half(v - __half2float(h));
    size_t b = (size_t)r * KE;
    Xe[b + c] = h; Xe[b + 512 + c] = l;
}

__global__ void expand_w4(const float* __restrict__ w0, const float* __restrict__ w1,
                          const float* __restrict__ w2, const float* __restrict__ w3,
                          __half* __restrict__ We) {
    int i = blockIdx.x * blockDim.x + threadIdx.x;
    if (i >= 4 * HID * HID) return;
    int m = i >> 18;
    int local = i & 262143;
    const float* W = (m == 0) ? w0 : (m == 1) ? w1 : (m == 2) ? w2 : w3;
    int r = local >> 9, c = local & 511;
    __half h = __float2half(W[r * HID + c]);
    size_t b = (size_t)m * HID * KE + (size_t)r * KE;
    We[b + c] = h; We[b + 512 + c] = h;
}

// ---------------------------------------------------------------------------
// HMMA GEMM: 128 x BN CTA tile, 8 warps, mma.sync.m16n8k16, XOR-swizzled
// smem, 3-stage cp.async ring. SPLIT (QKV): cols < 512 -> Cf fp32;
// cols >= 512 -> Ch fp16 (ld 1024).
// ---------------------------------------------------------------------------
template <int BN, bool SPLIT>
__global__ __launch_bounds__(256, 2) void gemm_hmma(
    const __half* __restrict__ A, const __half* __restrict__ B,
    const float* __restrict__ bias, float* __restrict__ Cf, __half* __restrict__ Ch)
{
    constexpr int NT = BN / 32;
    constexpr int STG_A = 16384;
    constexpr int STG_B = BN * 128;
    constexpr int STAGE = STG_A + STG_B;

    extern __shared__ char sm_raw[];
    const int tid = threadIdx.x;
    const int wid = tid >> 5, lane = tid & 31;
    const int bm = blockIdx.y * 128, bn = blockIdx.x * BN;
    const int wm = (wid & 1) * 64;
    const int wn = (wid >> 1) * (BN / 4);
    const uint32_t sbase = smem_u32(sm_raw);

    float acc[4][NT][4];
#pragma unroll
    for (int a = 0; a < 4; a++)
#pragma unroll
        for (int b = 0; b < NT; b++)
#pragma unroll
            for (int c = 0; c < 4; c++) acc[a][b][c] = 0.f;

    const int lr = tid >> 3;
    const int ls = tid & 7;

    auto issue = [&](int ch) {
        const __half* gA = A + (size_t)bm * KE + ch * KC;
        const __half* gB = B + (size_t)bn * KE + ch * KC;
        uint32_t sA = sbase + (ch % NSTAGE) * STAGE;
        uint32_t sB = sA + STG_A;
#pragma unroll
        for (int t = 0; t < 4; t++) {
            int row = lr + t * 32;
            uint32_t off = row * 128 + ((ls ^ (row & 7)) * 16);
            asm volatile("cp.async.cg.shared.global [%0], [%1], 16;"
                         :: "r"(sA + off), "l"(gA + (size_t)row * KE + ls * 8));
        }
#pragma unroll
        for (int t = 0; t < BN / 32; t++) {
            int row = lr + t * 32;
            uint32_t off = row * 128 + ((ls ^ (row & 7)) * 16);
            asm volatile("cp.async.cg.shared.global [%0], [%1], 16;"
                         :: "r"(sB + off), "l"(gB + (size_t)row * KE + ls * 8));
        }
        asm volatile("cp.async.commit_group;");
    };

    issue(0);
    issue(1);

    const int lrow = lane & 15;
    const int lseg = lane >> 4;

    for (int ch = 0; ch < NKCH; ++ch) {
        if (ch < NKCH - 1) asm volatile("cp.async.wait_group 1;");
        else               asm volatile("cp.async.wait_group 0;");
        __syncthreads();
        if (ch + 2 < NKCH) issue(ch + 2);

        const uint32_t sA = sbase + (ch % NSTAGE) * STAGE;
        const uint32_t sB = sA + STG_A;

#pragma unroll
        for (int k = 0; k < KC; k += 16) {
            const int seg = (k >> 3) + lseg;
            uint32_t ar[4][4];
#pragma unroll
            for (int mt = 0; mt < 4; mt++) {
                int row = wm + mt * 16 + lrow;
                uint32_t addr = sA + row * 128 + ((seg ^ (row & 7)) * 16);
                asm volatile("ldmatrix.sync.aligned.m8n8.x4.shared.b16 {%0,%1,%2,%3}, [%4];"
                             : "=r"(ar[mt][0]), "=r"(ar[mt][1]), "=r"(ar[mt][2]), "=r"(ar[mt][3])
                             : "r"(addr));
            }
            uint32_t br[NT / 2][4];
#pragma unroll
            for (int nt2 = 0; nt2 < NT / 2; nt2++) {
                int row = wn + nt2 * 16 + lrow;
                uint32_t addr = sB + row * 128 + ((seg ^ (row & 7)) * 16);
                asm volatile("ldmatrix.sync.aligned.m8n8.x4.shared.b16 {%0,%1,%2,%3}, [%4];"
                             : "=r"(br[nt2][0]), "=r"(br[nt2][1]), "=r"(br[nt2][2]), "=r"(br[nt2][3])
                             : "r"(addr));
            }
#pragma unroll
            for (int mt = 0; mt < 4; mt++)
#pragma unroll
                for (int nt = 0; nt < NT; nt++) {
                    uint32_t b0 = br[nt >> 1][nt & 1];
                    uint32_t b1 = br[nt >> 1][(nt & 1) + 2];
                    asm volatile(
                        "mma.sync.aligned.m16n8k16.row.col.f32.f16.f16.f32 "
                        "{%0,%1,%2,%3}, {%4,%5,%6,%7}, {%8,%9}, {%0,%1,%2,%3};"
                        : "+f"(acc[mt][nt][0]), "+f"(acc[mt][nt][1]),
                          "+f"(acc[mt][nt][2]), "+f"(acc[mt][nt][3])
                        : "r"(ar[mt][0]), "r"(ar[mt][1]), "r"(ar[mt][2]), "r"(ar[mt][3]),
                          "r"(b0), "r"(b1));
                }
        }
        __syncthreads();
    }

    const int r0 = bm + wm + (lane >> 2);
    const int c0 = bn + wn + (lane & 3) * 2;
#pragma unroll
    for (int nt = 0; nt < NT; nt++) {
        int col = c0 + nt * 8;
        float2 bb = *(const float2*)(bias + col);
#pragma unroll
        for (int mt = 0; mt < 4; mt++) {
            int row = r0 + mt * 16;
            float2 v0 = make_float2(acc[mt][nt][0] + bb.x, acc[mt][nt][1] + bb.y);
            float2 v1 = make_float2(acc[mt][nt][2] + bb.x, acc[mt][nt][3] + bb.y);
            if (SPLIT && bn >= 512) {
                int ch_col = col - 512;
                *(__half2*)(Ch + (size_t)row * 1024 + ch_col) = __floats2half2_rn(v0.x, v0.y);
                *(__half2*)(Ch + (size_t)(row + 8) * 1024 + ch_col) = __floats2half2_rn(v1.x, v1.y);
            } else {
                *(float2*)(Cf + (size_t)row * 512 + col) = v0;
                *(float2*)(Cf + (size_t)(row + 8) * 512 + col) = v1;
            }
        }
    }
}

// ---------------------------------------------------------------------------
// Tensor-core attention (structure identical to passing R8 kernel).
// Output -> Xe [hi|lo].
// ---------------------------------------------------------------------------
#define ATTN_SMEM (2 * MAXC * 128 + 8 * 2048)   // K 48K + V 48K + Q 16K = 112K

__device__ __forceinline__ void store_expanded(__half* Xe, int node, int col,
                                               float a, float b) {
    size_t row = (size_t)node * KE;
    __half ha = __float2half(a), hb = __float2half(b);
    __half la = __float2half(a - __half2float(ha));
    __half lb = __float2half(b - __half2float(hb));
    *(__half2*)(Xe + row + col) = __halves2half2(ha, hb);
    *(__half2*)(Xe + row + 512 + col) = __halves2half2(la, lb);
}

__global__ __launch_bounds__(256, 2) void attn_tc(
    const float* __restrict__ Qf, const __half* __restrict__ KVh,
    __half* __restrict__ Xe)
{
    extern __shared__ __align__(16) char smraw[];
    char* Kc = smraw;                     // [MAXC][128B]
    char* Vc = smraw + MAXC * 128;
    char* Qc = smraw + 2 * MAXC * 128;    // 8 warps x 2048B
    const uint32_t sK = smem_u32(Kc);
    const uint32_t sV = smem_u32(Vc);
    const uint32_t sQ = smem_u32(Qc);

    const int g = blockIdx.x, h = blockIdx.y;
    const int st = g_start[g];
    const int c = g_start[g + 1] - st;
    if (c <= 0) return;
    const int c16 = (c + 15) & ~15;
    const int nkt = c16 >> 4;
    const float fnpad = (float)(c16 - c);
    const int tid = threadIdx.x, wid = tid >> 5, lane = tid & 31;

    for (int idx = tid; idx < c16 * 8; idx += 256) {
        int r = idx >> 3, u = idx & 7;
        uint32_t off = r * 128 + ((u ^ (r & 7)) * 16);
        uint4 kv = make_uint4(0, 0, 0, 0), vv = make_uint4(0, 0, 0, 0);
        if (r < c) {
            const __half* src = KVh + (size_t)(st + r) * 1024 + h * HDIM + u * 8;
            kv = *(const uint4*)src;
            vv = *(const uint4*)(src + 512);
        }
        *(uint4*)(Kc + off) = kv;
        *(uint4*)(Vc + off) = vv;
    }
    __syncthreads();

    const int lrow = lane & 15;
    const int lseg = lane >> 4;
    const int ntiles = (c + 15) >> 4;
    const uint32_t qb32 = sQ + wid * 2048;
    char* qbc = Qc + wid * 2048;
    const float scale = 0.125f;

    for (int qt = wid; qt < ntiles; qt += 8) {
        for (int t = lane; t < 128; t += 32) {
            int row = t & 15, seg = t >> 4;
            int qrow = qt * 16 + row;
            if (qrow >= c) qrow = c - 1;
            const float4* qp = (const float4*)(Qf + (size_t)(st + qrow) * 512 + h * HDIM + seg * 8);
            float4 x0 = qp[0], x1 = qp[1];
            __half2 h0 = __floats2half2_rn(x0.x, x0.y);
            __half2 h1 = __floats2half2_rn(x0.z, x0.w);
            __half2 h2 = __floats2half2_rn(x1.x, x1.y);
            __half2 h3 = __floats2half2_rn(x1.z, x1.w);
            uint4 pk;
            pk.x = *(uint32_t*)&h0; pk.y = *(uint32_t*)&h1;
            pk.z = *(uint32_t*)&h2; pk.w = *(uint32_t*)&h3;
            *(uint4*)(qbc + row * 128 + ((seg ^ (row & 7)) * 16)) = pk;
        }
        __syncwarp();

        uint32_t aq[4][4];
#pragma unroll
        for (int ks = 0; ks < 4; ks++) {
            uint32_t addr = qb32 + lrow * 128 + (((ks * 2 + lseg) ^ (lrow & 7)) * 16);
            asm volatile("ldmatrix.sync.aligned.m8n8.x4.shared.b16 {%0,%1,%2,%3}, [%4];"
                         : "=r"(aq[ks][0]), "=r"(aq[ks][1]), "=r"(aq[ks][2]), "=r"(aq[ks][3])
                         : "r"(addr));
        }

        float oacc[8][4];
#pragma unroll
        for (int d = 0; d < 8; d++)
#pragma unroll
            for (int e = 0; e < 4; e++) oacc[d][e] = 0.f;
        float lr = 0.f, lr8 = 0.f;

        for (int kt = 0; kt < nkt; kt++) {
            const int krow = kt * 16 + lrow;
            float sacc[2][4];
#pragma unroll
            for (int nt = 0; nt < 2; nt++)
#pragma unroll
                for (int e = 0; e < 4; e++) sacc[nt][e] = 0.f;
#pragma unroll
            for (int ks = 0; ks < 4; ks++) {
                uint32_t addr = sK + krow * 128 + (((ks * 2 + lseg) ^ (krow & 7)) * 16);
                uint32_t bk[4];
                asm volatile("ldmatrix.sync.aligned.m8n8.x4.shared.b16 {%0,%1,%2,%3}, [%4];"
                             : "=r"(bk[0]), "=r"(bk[1]), "=r"(bk[2]), "=r"(bk[3])
                             : "r"(addr));
#pragma unroll
                for (int nt = 0; nt < 2; nt++) {
                    asm volatile(
                        "mma.sync.aligned.m16n8k16.row.col.f32.f16.f16.f32 "
                        "{%0,%1,%2,%3}, {%4,%5,%6,%7}, {%8,%9}, {%0,%1,%2,%3};"
                        : "+f"(sacc[nt][0]), "+f"(sacc[nt][1]),
                          "+f"(sacc[nt][2]), "+f"(sacc[nt][3])
                        : "r"(aq[ks][0]), "r"(aq[ks][1]), "r"(aq[ks][2]), "r"(aq[ks][3]),
                          "r"(bk[nt]), "r"(bk[nt + 2]));
                }
            }
            float p00 = __expf(fminf(sacc[0][0] * scale, 10.f));
            float p01 = __expf(fminf(sacc[0][1] * scale, 10.f));
            float p02 = __expf(fminf(sacc[0][2] * scale, 10.f));
            float p03 = __expf(fminf(sacc[0][3] * scale, 10.f));
            float p10 = __expf(fminf(sacc[1][0] * scale, 10.f));
            float p11 = __expf(fminf(sacc[1][1] * scale, 10.f));
            float p12 = __expf(fminf(sacc[1][2] * scale, 10.f));
            float p13 = __expf(fminf(sacc[1][3] * scale, 10.f));
            __half2 a0 = __floats2half2_rn(p00, p01);
            __half2 a1 = __floats2half2_rn(p02, p03);
            __half2 a2 = __floats2half2_rn(p10, p11);
            __half2 a3 = __floats2half2_rn(p12, p13);
            float2 f;
            f = __half22float2(a0); lr += f.x + f.y;
            f = __half22float2(a1); lr8 += f.x + f.y;
            f = __half22float2(a2); lr += f.x + f.y;
            f = __half22float2(a3); lr8 += f.x + f.y;
            uint32_t pa0 = *(uint32_t*)&a0, pa1 = *(uint32_t*)&a1;
            uint32_t pa2 = *(uint32_t*)&a2, pa3 = *(uint32_t*)&a3;

#pragma unroll
            for (int v16 = 0; v16 < 4; v16++) {
                uint32_t addr = sV + krow * 128 + (((v16 * 2 + lseg) ^ (krow & 7)) * 16);
                uint32_t bv[4];
                asm volatile("ldmatrix.sync.aligned.m8n8.x4.trans.shared.b16 {%0,%1,%2,%3}, [%4];"
                             : "=r"(bv[0]), "=r"(bv[1]), "=r"(bv[2]), "=r"(bv[3])
                             : "r"(addr));
                asm volatile(
                    "mma.sync.aligned.m16n8k16.row.col.f32.f16.f16.f32 "
                    "{%0,%1,%2,%3}, {%4,%5,%6,%7}, {%8,%9}, {%0,%1,%2,%3};"
                    : "+f"(oacc[v16 * 2][0]), "+f"(oacc[v16 * 2][1]),
                      "+f"(oacc[v16 * 2][2]), "+f"(oacc[v16 * 2][3])
                    : "r"(pa0), "r"(pa1), "r"(pa2), "r"(pa3),
                      "r"(bv[0]), "r"(bv[1]));
                asm volatile(
                    "mma.sync.aligned.m16n8k16.row.col.f32.f16.f16.f32 "
                    "{%0,%1,%2,%3}, {%4,%5,%6,%7}, {%8,%9}, {%0,%1,%2,%3};"
                    : "+f"(oacc[v16 * 2 + 1][0]), "+f"(oacc[v16 * 2 + 1][1]),
                      "+f"(oacc[v16 * 2 + 1][2]), "+f"(oacc[v16 * 2 + 1][3])
                    : "r"(pa0), "r"(pa1), "r"(pa2), "r"(pa3),
                      "r"(bv[2]), "r"(bv[3]));
            }
        }

        lr += __shfl_xor_sync(0xffffffffu, lr, 1);
        lr += __shfl_xor_sync(0xffffffffu, lr, 2);
        lr8 += __shfl_xor_sync(0xffffffffu, lr8, 1);
        lr8 += __shfl_xor_sync(0xffffffffu, lr8, 2);
        float inv = 1.f / (lr - fnpad);
        float inv8 = 1.f / (lr8 - fnpad);

        const int r0 = qt * 16 + (lane >> 2);
#pragma unroll
        for (int dt = 0; dt < 8; dt++) {
            int col = h * HDIM + dt * 8 + (lane & 3) * 2;
            if (r0 < c)
                store_expanded(Xe, st + r0, col, oacc[dt][0] * inv, oacc[dt][1] * inv);
            if (r0 + 8 < c)
                store_expanded(Xe, st + r0 + 8, col, oacc[dt][2] * inv8, oacc[dt][3] * inv8);
        }
    }
}

// ---------------------------------------------------------------------------
extern "C" void kernel_launch(void* const* d_in, const int* in_sizes, int n_in,
                              void* d_out, int out_size) {
    const float* x  = (const float*)d_in[0];
    const void*  bt = d_in[1];
    const float* wq = (const float*)d_in[2];
    const float* bq = (const float*)d_in[3];
    const float* wk = (const float*)d_in[4];
    const float* bk = (const float*)d_in[5];
    const float* wv = (const float*)d_in[6];
    const float* bv = (const float*)d_in[7];
    const float* wo = (const float*)d_in[8];
    const float* bo = (const float*)d_in[9];
    float* out = (float*)d_out;

    float *Qf, *bcat;
    __half *KVh, *Xe, *We;
    cudaGetSymbolAddress((void**)&Qf, g_Qf);
    cudaGetSymbolAddress((void**)&KVh, g_KVh);
    cudaGetSymbolAddress((void**)&Xe, g_Xe);
    cudaGetSymbolAddress((void**)&We, g_We);
    cudaGetSymbolAddress((void**)&bcat, g_bcat);
    __half* Weo = We + 3 * (size_t)HID * KE;

    const int smem128 = NSTAGE * (16384 + 128 * 128);  // 98304
    const int smem64  = NSTAGE * (16384 + 64 * 128);   // 73728
    cudaFuncSetAttribute(gemm_hmma<128, true>,
                         cudaFuncAttributeMaxDynamicSharedMemorySize, smem128);
    cudaFuncSetAttribute(gemm_hmma<64, false>,
                         cudaFuncAttributeMaxDynamicSharedMemorySize, smem64);
    cudaFuncSetAttribute(attn_tc,
                         cudaFuncAttributeMaxDynamicSharedMemorySize, ATTN_SMEM);

    starts_kernel<<<(NNODES + 255) / 256, 256>>>(bt, NNODES);
    bias_cat<<<1, HID>>>(bq, bk, bv);

    const int xtot = NNODES * HID;
    expand_a<<<(xtot + 255) / 256, 256>>>(x, Xe, xtot);
    expand_w4<<<(4 * HID * HID + 255) / 256, 256>>>(wq, wk, wv, wo, We);

    // fused Q|K|V projection: N = 1536 (Q -> fp32, K|V -> fp16)
    gemm_hmma<128, true><<<dim3(12, 80), 256, smem128>>>(Xe, We, bcat, Qf, KVh);

    // tensor-core attention; writes O directly in expanded fp16 form into Xe
    attn_tc<<<dim3(NGRAPH, HEADS), 256, ATTN_SMEM>>>(Qf, KVh, Xe);

    // output projection: 128x64 tiles -> 640 CTAs
    gemm_hmma<64, false><<<dim3(8, 80), 256, smem64>>>(Xe, Weo, bo, out, nullptr);
}

// round 10
// speedup vs baseline: 5.4901x; 1.1415x over previous
#include <cuda_runtime.h>
#include <cuda_fp16.h>
#include <cstdint>

#define NNODES 10240
#define NGRAPH 64
#define HID 512
#define HEADS 8
#define HDIM 64
#define MAXC 384

#define KE 1024              // expanded K: A=[hi|lo], B=[hi|hi] -> C = x * fp16(W)
#define KC 64                // halves per K-chunk (128B per row)
#define NKCH (KE / KC)       // 16
#define NSTAGE 3

// ---------------------------------------------------------------------------
// Scratch (device globals: no allocation allowed)
// ---------------------------------------------------------------------------
__device__ float g_Qf[(size_t)NNODES * HID];                      // Q fp32
__device__ __align__(16) __half g_KVh[(size_t)NNODES * 1024];     // K|V fp16
__device__ __align__(16) __half g_Xe[(size_t)NNODES * KE];        // x / O expanded [hi|lo]
__device__ __align__(16) __half g_We[4][(size_t)HID * KE];        // wq,wk,wv,wo expanded [hi|hi]
__device__ float g_bcat[3 * HID];
__device__ int g_start[NGRAPH + 2];

// ---------------------------------------------------------------------------
__device__ __forceinline__ uint32_t smem_u32(const void* p) {
    uint32_t a;
    asm("{ .reg .u64 t; cvta.to.shared.u64 t, %1; cvt.u32.u64 %0, t; }" : "=r"(a) : "l"(p));
    return a;
}

// ---------------------------------------------------------------------------
// Segment starts from sorted batch (int32 or int64 storage).
// ---------------------------------------------------------------------------
__global__ void starts_kernel(const void* bptr, int n) {
    const int* b32 = (const int*)bptr;
    const long long* b64 = (const long long*)bptr;
    const bool is64 = (b32[n - 1] == 0);
    int i = blockIdx.x * blockDim.x + threadIdx.x;
    if (i >= n) return;
    int bi = is64 ? (int)b64[i] : b32[i];
    int bp = (i == 0) ? -1 : (is64 ? (int)b64[i - 1] : b32[i - 1]);
    for (int g = bp + 1; g <= bi; ++g) g_start[g] = i;
    if (i == n - 1)
        for (int g = bi + 1; g <= NGRAPH; ++g) g_start[g] = n;
}

__global__ void bias_cat(const float* bq, const float* bk, const float* bv) {
    int i = threadIdx.x;
    g_bcat[i] = bq[i];
    g_bcat[HID + i] = bk[i];
    g_bcat[2 * HID + i] = bv[i];
}

// ---------------------------------------------------------------------------
// fp32 -> fp16 expansion. A side [hi|lo]; B side [hi|hi].
// ---------------------------------------------------------------------------
__global__ void expand_a(const float* __restrict__ X, __half* __restrict__ Xe, int total) {
    int i = blockIdx.x * blockDim.x + threadIdx.x;
    if (i >= total) return;
    int r = i >> 9, c = i & 511;
    float v = X[i];
    __half h = __float2half(v);
    __half l = __float2half(v - __half2float(h));
    size_t b = (size_t)r * KE;
    Xe[b + c] = h; Xe[b + 512 + c] = l;
}

__global__ void expand_w4(const float* __restrict__ w0, const float* __restrict__ w1,
                          const float* __restrict__ w2, const float* __restrict__ w3,
                          __half* __restrict__ We) {
    int i = blockIdx.x * blockDim.x + threadIdx.x;
    if (i >= 4 * HID * HID) return;
    int m = i >> 18;
    int local = i & 262143;
    const float* W = (m == 0) ? w0 : (m == 1) ? w1 : (m == 2) ? w2 : w3;
    int r = local >> 9, c = local & 511;
    __half h = __float2half(W[r * HID + c]);
    size_t b = (size_t)m * HID * KE + (size_t)r * KE;
    We[b + c] = h; We[b + 512 + c] = h;
}

// ---------------------------------------------------------------------------
// HMMA GEMM: 128 x BN CTA tile, 4 warps (2m x 2n), warp tile 64 x BN/2,
// mma.sync.m16n8k16, XOR-swizzled smem, 3-stage cp.async ring.
// 4-warp layout halves redundant A/B fragment re-reads vs 8-warp 2x4.
// SPLIT (QKV): cols < 512 -> Cf fp32, full K; cols >= 512 -> Ch fp16,
// HALF K (drops lo(x) term for K/V: ~2^-12 rel, below their fp16 storage).
// ---------------------------------------------------------------------------
template <int BN, bool SPLIT>
__global__ __launch_bounds__(128, 2) void gemm_hmma(
    const __half* __restrict__ A, const __half* __restrict__ B,
    const float* __restrict__ bias, float* __restrict__ Cf, __half* __restrict__ Ch)
{
    constexpr int NT = BN / 16;            // n-subtiles (8 cols) per warp
    constexpr int STG_A = 16384;
    constexpr int STG_B = BN * 128;
    constexpr int STAGE = STG_A + STG_B;

    extern __shared__ char sm_raw[];
    const int tid = threadIdx.x;
    const int wid = tid >> 5, lane = tid & 31;
    const int bm = blockIdx.y * 128, bn = blockIdx.x * BN;
    const int wm = (wid & 1) * 64;
    const int wn = (wid >> 1) * (BN / 2);
    const uint32_t sbase = smem_u32(sm_raw);

    const int nkch = (SPLIT && bn >= 512) ? (NKCH / 2) : NKCH;

    float acc[4][NT][4];
#pragma unroll
    for (int a = 0; a < 4; a++)
#pragma unroll
        for (int b = 0; b < NT; b++)
#pragma unroll
            for (int c = 0; c < 4; c++) acc[a][b][c] = 0.f;

    const int lr = tid >> 3;      // 0..15 row group
    const int ls = tid & 7;       // 0..7 16B segment

    auto issue = [&](int ch) {
        const __half* gA = A + (size_t)bm * KE + ch * KC;
        const __half* gB = B + (size_t)bn * KE + ch * KC;
        uint32_t sA = sbase + (ch % NSTAGE) * STAGE;
        uint32_t sB = sA + STG_A;
#pragma unroll
        for (int t = 0; t < 8; t++) {
            int row = lr + t * 16;
            uint32_t off = row * 128 + ((ls ^ (row & 7)) * 16);
            asm volatile("cp.async.cg.shared.global [%0], [%1], 16;"
                         :: "r"(sA + off), "l"(gA + (size_t)row * KE + ls * 8));
        }
#pragma unroll
        for (int t = 0; t < BN / 16; t++) {
            int row = lr + t * 16;
            uint32_t off = row * 128 + ((ls ^ (row & 7)) * 16);
            asm volatile("cp.async.cg.shared.global [%0], [%1], 16;"
                         :: "r"(sB + off), "l"(gB + (size_t)row * KE + ls * 8));
        }
        asm volatile("cp.async.commit_group;");
    };

    issue(0);
    issue(1);

    const int lrow = lane & 15;
    const int lseg = lane >> 4;

    for (int ch = 0; ch < nkch; ++ch) {
        if (ch < nkch - 1) asm volatile("cp.async.wait_group 1;");
        else               asm volatile("cp.async.wait_group 0;");
        __syncthreads();
        if (ch + 2 < nkch) issue(ch + 2);

        const uint32_t sA = sbase + (ch % NSTAGE) * STAGE;
        const uint32_t sB = sA + STG_A;

#pragma unroll
        for (int k = 0; k < KC; k += 16) {
            const int seg = (k >> 3) + lseg;
            uint32_t ar[4][4];
#pragma unroll
            for (int mt = 0; mt < 4; mt++) {
                int row = wm + mt * 16 + lrow;
                uint32_t addr = sA + row * 128 + ((seg ^ (row & 7)) * 16);
                asm volatile("ldmatrix.sync.aligned.m8n8.x4.shared.b16 {%0,%1,%2,%3}, [%4];"
                             : "=r"(ar[mt][0]), "=r"(ar[mt][1]), "=r"(ar[mt][2]), "=r"(ar[mt][3])
                             : "r"(addr));
            }
            uint32_t br[NT / 2][4];
#pragma unroll
            for (int nt2 = 0; nt2 < NT / 2; nt2++) {
                int row = wn + nt2 * 16 + lrow;
                uint32_t addr = sB + row * 128 + ((seg ^ (row & 7)) * 16);
                asm volatile("ldmatrix.sync.aligned.m8n8.x4.shared.b16 {%0,%1,%2,%3}, [%4];"
                             : "=r"(br[nt2][0]), "=r"(br[nt2][1]), "=r"(br[nt2][2]), "=r"(br[nt2][3])
                             : "r"(addr));
            }
#pragma unroll
            for (int mt = 0; mt < 4; mt++)
#pragma unroll
                for (int nt = 0; nt < NT; nt++) {
                    uint32_t b0 = br[nt >> 1][nt & 1];
                    uint32_t b1 = br[nt >> 1][(nt & 1) + 2];
                    asm volatile(
                        "mma.sync.aligned.m16n8k16.row.col.f32.f16.f16.f32 "
                        "{%0,%1,%2,%3}, {%4,%5,%6,%7}, {%8,%9}, {%0,%1,%2,%3};"
                        : "+f"(acc[mt][nt][0]), "+f"(acc[mt][nt][1]),
                          "+f"(acc[mt][nt][2]), "+f"(acc[mt][nt][3])
                        : "r"(ar[mt][0]), "r"(ar[mt][1]), "r"(ar[mt][2]), "r"(ar[mt][3]),
                          "r"(b0), "r"(b1));
                }
        }
        __syncthreads();
    }

    const int r0 = bm + wm + (lane >> 2);
    const int c0 = bn + wn + (lane & 3) * 2;
#pragma unroll
    for (int nt = 0; nt < NT; nt++) {
        int col = c0 + nt * 8;
        float2 bb = *(const float2*)(bias + col);
#pragma unroll
        for (int mt = 0; mt < 4; mt++) {
            int row = r0 + mt * 16;
            float2 v0 = make_float2(acc[mt][nt][0] + bb.x, acc[mt][nt][1] + bb.y);
            float2 v1 = make_float2(acc[mt][nt][2] + bb.x, acc[mt][nt][3] + bb.y);
            if (SPLIT && bn >= 512) {
                int ch_col = col - 512;
                *(__half2*)(Ch + (size_t)row * 1024 + ch_col) = __floats2half2_rn(v0.x, v0.y);
                *(__half2*)(Ch + (size_t)(row + 8) * 1024 + ch_col) = __floats2half2_rn(v1.x, v1.y);
            } else {
                *(float2*)(Cf + (size_t)row * 512 + col) = v0;
                *(float2*)(Cf + (size_t)(row + 8) * 512 + col) = v1;
            }
        }
    }
}

// ---------------------------------------------------------------------------
// Tensor-core attention (unchanged from passing R9 kernel). Output -> Xe [hi|lo].
// ---------------------------------------------------------------------------
#define ATTN_SMEM (2 * MAXC * 128 + 8 * 2048)   // K 48K + V 48K + Q 16K = 112K

__device__ __forceinline__ void store_expanded(__half* Xe, int node, int col,
                                               float a, float b) {
    size_t row = (size_t)node * KE;
    __half ha = __float2half(a), hb = __float2half(b);
    __half la = __float2half(a - __half2float(ha));
    __half lb = __float2half(b - __half2float(hb));
    *(__half2*)(Xe + row + col) = __halves2half2(ha, hb);
    *(__half2*)(Xe + row + 512 + col) = __halves2half2(la, lb);
}

__global__ __launch_bounds__(256, 2) void attn_tc(
    const float* __restrict__ Qf, const __half* __restrict__ KVh,
    __half* __restrict__ Xe)
{
    extern __shared__ __align__(16) char smraw[];
    char* Kc = smraw;                     // [MAXC][128B]
    char* Vc = smraw + MAXC * 128;
    char* Qc = smraw + 2 * MAXC * 128;    // 8 warps x 2048B
    const uint32_t sK = smem_u32(Kc);
    const uint32_t sV = smem_u32(Vc);
    const uint32_t sQ = smem_u32(Qc);

    const int g = blockIdx.x, h = blockIdx.y;
    const int st = g_start[g];
    const int c = g_start[g + 1] - st;
    if (c <= 0) return;
    const int c16 = (c + 15) & ~15;
    const int nkt = c16 >> 4;
    const float fnpad = (float)(c16 - c);
    const int tid = threadIdx.x, wid = tid >> 5, lane = tid & 31;

    for (int idx = tid; idx < c16 * 8; idx += 256) {
        int r = idx >> 3, u = idx & 7;
        uint32_t off = r * 128 + ((u ^ (r & 7)) * 16);
        uint4 kv = make_uint4(0, 0, 0, 0), vv = make_uint4(0, 0, 0, 0);
        if (r < c) {
            const __half* src = KVh + (size_t)(st + r) * 1024 + h * HDIM + u * 8;
            kv = *(const uint4*)src;
            vv = *(const uint4*)(src + 512);
        }
        *(uint4*)(Kc + off) = kv;
        *(uint4*)(Vc + off) = vv;
    }
    __syncthreads();

    const int lrow = lane & 15;
    const int lseg = lane >> 4;
    const int ntiles = (c + 15) >> 4;
    const uint32_t qb32 = sQ + wid * 2048;
    char* qbc = Qc + wid * 2048;
    const float scale = 0.125f;

    for (int qt = wid; qt < ntiles; qt += 8) {
        for (int t = lane; t < 128; t += 32) {
            int row = t & 15, seg = t >> 4;
            int qrow = qt * 16 + row;
            if (qrow >= c) qrow = c - 1;
            const float4* qp = (const float4*)(Qf + (size_t)(st + qrow) * 512 + h * HDIM + seg * 8);
            float4 x0 = qp[0], x1 = qp[1];
            __half2 h0 = __floats2half2_rn(x0.x, x0.y);
            __half2 h1 = __floats2half2_rn(x0.z, x0.w);
            __half2 h2 = __floats2half2_rn(x1.x, x1.y);
            __half2 h3 = __floats2half2_rn(x1.z, x1.w);
            uint4 pk;
            pk.x = *(uint32_t*)&h0; pk.y = *(uint32_t*)&h1;
            pk.z = *(uint32_t*)&h2; pk.w = *(uint32_t*)&h3;
            *(uint4*)(qbc + row * 128 + ((seg ^ (row & 7)) * 16)) = pk;
        }
        __syncwarp();

        uint32_t aq[4][4];
#pragma unroll
        for (int ks = 0; ks < 4; ks++) {
            uint32_t addr = qb32 + lrow * 128 + (((ks * 2 + lseg) ^ (lrow & 7)) * 16);
            asm volatile("ldmatrix.sync.aligned.m8n8.x4.shared.b16 {%0,%1,%2,%3}, [%4];"
                         : "=r"(aq[ks][0]), "=r"(aq[ks][1]), "=r"(aq[ks][2]), "=r"(aq[ks][3])
                         : "r"(addr));
        }

        float oacc[8][4];
#pragma unroll
        for (int d = 0; d < 8; d++)
#pragma unroll
            for (int e = 0; e < 4; e++) oacc[d][e] = 0.f;
        float lr = 0.f, lr8 = 0.f;

        for (int kt = 0; kt < nkt; kt++) {
            const int krow = kt * 16 + lrow;
            float sacc[2][4];
#pragma unroll
            for (int nt = 0; nt < 2; nt++)
#pragma unroll
                for (int e = 0; e < 4; e++) sacc[nt][e] = 0.f;
#pragma unroll
            for (int ks = 0; ks < 4; ks++) {
                uint32_t addr = sK + krow * 128 + (((ks * 2 + lseg) ^ (krow & 7)) * 16);
                uint32_t bk[4];
                asm volatile("ldmatrix.sync.aligned.m8n8.x4.shared.b16 {%0,%1,%2,%3}, [%4];"
                             : "=r"(bk[0]), "=r"(bk[1]), "=r"(bk[2]), "=r"(bk[3])
                             : "r"(addr));
#pragma unroll
                for (int nt = 0; nt < 2; nt++) {
                    asm volatile(
                        "mma.sync.aligned.m16n8k16.row.col.f32.f16.f16.f32 "
                        "{%0,%1,%2,%3}, {%4,%5,%6,%7}, {%8,%9}, {%0,%1,%2,%3};"
                        : "+f"(sacc[nt][0]), "+f"(sacc[nt][1]),
                          "+f"(sacc[nt][2]), "+f"(sacc[nt][3])
                        : "r"(aq[ks][0]), "r"(aq[ks][1]), "r"(aq[ks][2]), "r"(aq[ks][3]),
                          "r"(bk[nt]), "r"(bk[nt + 2]));
                }
            }
            float p00 = __expf(fminf(sacc[0][0] * scale, 10.f));
            float p01 = __expf(fminf(sacc[0][1] * scale, 10.f));
            float p02 = __expf(fminf(sacc[0][2] * scale, 10.f));
            float p03 = __expf(fminf(sacc[0][3] * scale, 10.f));
            float p10 = __expf(fminf(sacc[1][0] * scale, 10.f));
            float p11 = __expf(fminf(sacc[1][1] * scale, 10.f));
            float p12 = __expf(fminf(sacc[1][2] * scale, 10.f));
            float p13 = __expf(fminf(sacc[1][3] * scale, 10.f));
            __half2 a0 = __floats2half2_rn(p00, p01);
            __half2 a1 = __floats2half2_rn(p02, p03);
            __half2 a2 = __floats2half2_rn(p10, p11);
            __half2 a3 = __floats2half2_rn(p12, p13);
            float2 f;
            f = __half22float2(a0); lr += f.x + f.y;
            f = __half22float2(a1); lr8 += f.x + f.y;
            f = __half22float2(a2); lr += f.x + f.y;
            f = __half22float2(a3); lr8 += f.x + f.y;
            uint32_t pa0 = *(uint32_t*)&a0, pa1 = *(uint32_t*)&a1;
            uint32_t pa2 = *(uint32_t*)&a2, pa3 = *(uint32_t*)&a3;

#pragma unroll
            for (int v16 = 0; v16 < 4; v16++) {
                uint32_t addr = sV + krow * 128 + (((v16 * 2 + lseg) ^ (krow & 7)) * 16);
                uint32_t bv[4];
                asm volatile("ldmatrix.sync.aligned.m8n8.x4.trans.shared.b16 {%0,%1,%2,%3}, [%4];"
                             : "=r"(bv[0]), "=r"(bv[1]), "=r"(bv[2]), "=r"(bv[3])
                             : "r"(addr));
                asm volatile(
                    "mma.sync.aligned.m16n8k16.row.col.f32.f16.f16.f32 "
                    "{%0,%1,%2,%3}, {%4,%5,%6,%7}, {%8,%9}, {%0,%1,%2,%3};"
                    : "+f"(oacc[v16 * 2][0]), "+f"(oacc[v16 * 2][1]),
                      "+f"(oacc[v16 * 2][2]), "+f"(oacc[v16 * 2][3])
                    : "r"(pa0), "r"(pa1), "r"(pa2), "r"(pa3),
                      "r"(bv[0]), "r"(bv[1]));
                asm volatile(
                    "mma.sync.aligned.m16n8k16.row.col.f32.f16.f16.f32 "
                    "{%0,%1,%2,%3}, {%4,%5,%6,%7}, {%8,%9}, {%0,%1,%2,%3};"
                    : "+f"(oacc[v16 * 2 + 1][0]), "+f"(oacc[v16 * 2 + 1][1]),
                      "+f"(oacc[v16 * 2 + 1][2]), "+f"(oacc[v16 * 2 + 1][3])
                    : "r"(pa0), "r"(pa1), "r"(pa2), "r"(pa3),
                      "r"(bv[2]), "r"(bv[3]));
            }
        }

        lr += __shfl_xor_sync(0xffffffffu, lr, 1);
        lr += __shfl_xor_sync(0xffffffffu, lr, 2);
        lr8 += __shfl_xor_sync(0xffffffffu, lr8, 1);
        lr8 += __shfl_xor_sync(0xffffffffu, lr8, 2);
        float inv = 1.f / (lr - fnpad);
        float inv8 = 1.f / (lr8 - fnpad);

        const int r0 = qt * 16 + (lane >> 2);
#pragma unroll
        for (int dt = 0; dt < 8; dt++) {
            int col = h * HDIM + dt * 8 + (lane & 3) * 2;
            if (r0 < c)
                store_expanded(Xe, st + r0, col, oacc[dt][0] * inv, oacc[dt][1] * inv);
            if (r0 + 8 < c)
                store_expanded(Xe, st + r0 + 8, col, oacc[dt][2] * inv8, oacc[dt][3] * inv8);
        }
    }
}

// ---------------------------------------------------------------------------
extern "C" void kernel_launch(void* const* d_in, const int* in_sizes, int n_in,
                              void* d_out, int out_size) {
    const float* x  = (const float*)d_in[0];
    const void*  bt = d_in[1];
    const float* wq = (const float*)d_in[2];
    const float* bq = (const float*)d_in[3];
    const float* wk = (const float*)d_in[4];
    const float* bk = (const float*)d_in[5];
    const float* wv = (const float*)d_in[6];
    const float* bv = (const float*)d_in[7];
    const float* wo = (const float*)d_in[8];
    const float* bo = (const float*)d_in[9];
    float* out = (float*)d_out;

    float *Qf, *bcat;
    __half *KVh, *Xe, *We;
    cudaGetSymbolAddress((void**)&Qf, g_Qf);
    cudaGetSymbolAddress((void**)&KVh, g_KVh);
    cudaGetSymbolAddress((void**)&Xe, g_Xe);
    cudaGetSymbolAddress((void**)&We, g_We);
    cudaGetSymbolAddress((void**)&bcat, g_bcat);
    __half* Weo = We + 3 * (size_t)HID * KE;

    const int smem128 = NSTAGE * (16384 + 128 * 128);  // 98304
    const int smem64  = NSTAGE * (16384 + 64 * 128);   // 73728
    cudaFuncSetAttribute(gemm_hmma<128, true>,
                         cudaFuncAttributeMaxDynamicSharedMemorySize, smem128);
    cudaFuncSetAttribute(gemm_hmma<64, false>,
                         cudaFuncAttributeMaxDynamicSharedMemorySize, smem64);
    cudaFuncSetAttribute(attn_tc,
                         cudaFuncAttributeMaxDynamicSharedMemorySize, ATTN_SMEM);

    starts_kernel<<<(NNODES + 255) / 256, 256>>>(bt, NNODES);
    bias_cat<<<1, HID>>>(bq, bk, bv);

    const int xtot = NNODES * HID;
    expand_a<<<(xtot + 255) / 256, 256>>>(x, Xe, xtot);
    expand_w4<<<(4 * HID * HID + 255) / 256, 256>>>(wq, wk, wv, wo, We);

    // fused Q|K|V projection: N = 1536 (Q fp32 full-K; K|V fp16 half-K)
    gemm_hmma<128, true><<<dim3(12, 80), 128, smem128>>>(Xe, We, bcat, Qf, KVh);

    // tensor-core attention; writes O directly in expanded fp16 form into Xe
    attn_tc<<<dim3(NGRAPH, HEADS), 256, ATTN_SMEM>>>(Qf, KVh, Xe);

    // output projection: 128x64 tiles -> 640 CTAs
    gemm_hmma<64, false><<<dim3(8, 80), 128, smem64>>>(Xe, Weo, bo, out, nullptr);
}

// round 11
// speedup vs baseline: 6.3924x; 1.1644x over previous
#include <cuda_runtime.h>
#include <cuda_fp16.h>
#include <cstdint>

#define NNODES 10240
#define NGRAPH 64
#define HID 512
#define HEADS 8
#define HDIM 64
#define MAXC 384

#define KE 1024              // Xe layout: [hi|lo] (lo used only by out-proj)
#define KC 64                // halves per K-chunk (128B per row)
#define NSTAGE 3

// ---------------------------------------------------------------------------
// Scratch (device globals: no allocation allowed)
// ---------------------------------------------------------------------------
__device__ __align__(16) __half g_QKVh[(size_t)NNODES * 1536];    // Q|K|V fp16
__device__ __align__(16) __half g_Xe[(size_t)NNODES * KE];        // x / O expanded [hi|lo]
__device__ __align__(16) __half g_We[4][(size_t)HID * KE];        // wq,wk,wv,wo [hi|hi]
__device__ float g_bcat[3 * HID];
__device__ int g_start[NGRAPH + 2];

// ---------------------------------------------------------------------------
__device__ __forceinline__ uint32_t smem_u32(const void* p) {
    uint32_t a;
    asm("{ .reg .u64 t; cvta.to.shared.u64 t, %1; cvt.u32.u64 %0, t; }" : "=r"(a) : "l"(p));
    return a;
}

// ---------------------------------------------------------------------------
// Segment starts from sorted batch (int32 or int64 storage).
// ---------------------------------------------------------------------------
__global__ void starts_kernel(const void* bptr, int n) {
    const int* b32 = (const int*)bptr;
    const long long* b64 = (const long long*)bptr;
    const bool is64 = (b32[n - 1] == 0);
    int i = blockIdx.x * blockDim.x + threadIdx.x;
    if (i >= n) return;
    int bi = is64 ? (int)b64[i] : b32[i];
    int bp = (i == 0) ? -1 : (is64 ? (int)b64[i - 1] : b32[i - 1]);
    for (int g = bp + 1; g <= bi; ++g) g_start[g] = i;
    if (i == n - 1)
        for (int g = bi + 1; g <= NGRAPH; ++g) g_start[g] = n;
}

__global__ void bias_cat(const float* bq, const float* bk, const float* bv) {
    int i = threadIdx.x;
    g_bcat[i] = bq[i];
    g_bcat[HID + i] = bk[i];
    g_bcat[2 * HID + i] = bv[i];
}

// ---------------------------------------------------------------------------
// x -> fp16 hi only (lo is dead: QKV uses hi(x); out-proj input is O).
// ---------------------------------------------------------------------------
__global__ void expand_x(const float* __restrict__ X, __half* __restrict__ Xe, int total) {
    int i = blockIdx.x * blockDim.x + threadIdx.x;
    if (i >= total) return;
    int r = i >> 9, c = i & 511;
    Xe[(size_t)r * KE + c] = __float2half(X[i]);
}

__global__ void expand_w4(const float* __restrict__ w0, const float* __restrict__ w1,
                          const float* __restrict__ w2, const float* __restrict__ w3,
                          __half* __restrict__ We) {
    int i = blockIdx.x * blockDim.x + threadIdx.x;
    if (i >= 4 * HID * HID) return;
    int m = i >> 18;
    int local = i & 262143;
    const float* W = (m == 0) ? w0 : (m == 1) ? w1 : (m == 2) ? w2 : w3;
    int r = local >> 9, c = local & 511;
    __half h = __float2half(W[r * HID + c]);
    size_t b = (size_t)m * HID * KE + (size_t)r * KE;
    We[b + c] = h; We[b + 512 + c] = h;
}

// ---------------------------------------------------------------------------
// HMMA GEMM: 128 x BN CTA tile, 4 warps (2m x 2n), warp tile 64 x BN/2,
// mma.sync.m16n8k16, XOR-swizzled smem, 3-stage cp.async ring.
// NCH K-chunks; HALFOUT -> fp16 stores (ldc), else fp32 (ldc).
// ---------------------------------------------------------------------------
template <int BN, int NCH, bool HALFOUT>
__global__ __launch_bounds__(128, 2) void gemm_hmma(
    const __half* __restrict__ A, const __half* __restrict__ B,
    const float* __restrict__ bias, float* __restrict__ Cf,
    __half* __restrict__ Ch, int ldc)
{
    constexpr int NT = BN / 16;            // n-subtiles (8 cols) per warp
    constexpr int STG_A = 16384;
    constexpr int STG_B = BN * 128;
    constexpr int STAGE = STG_A + STG_B;

    extern __shared__ char sm_raw[];
    const int tid = threadIdx.x;
    const int wid = tid >> 5, lane = tid & 31;
    const int bm = blockIdx.y * 128, bn = blockIdx.x * BN;
    const int wm = (wid & 1) * 64;
    const int wn = (wid >> 1) * (BN / 2);
    const uint32_t sbase = smem_u32(sm_raw);

    float acc[4][NT][4];
#pragma unroll
    for (int a = 0; a < 4; a++)
#pragma unroll
        for (int b = 0; b < NT; b++)
#pragma unroll
            for (int c = 0; c < 4; c++) acc[a][b][c] = 0.f;

    const int lr = tid >> 3;      // 0..15 row group
    const int ls = tid & 7;       // 0..7 16B segment

    auto issue = [&](int ch) {
        const __half* gA = A + (size_t)bm * KE + ch * KC;
        const __half* gB = B + (size_t)bn * KE + ch * KC;
        uint32_t sA = sbase + (ch % NSTAGE) * STAGE;
        uint32_t sB = sA + STG_A;
#pragma unroll
        for (int t = 0; t < 8; t++) {
            int row = lr + t * 16;
            uint32_t off = row * 128 + ((ls ^ (row & 7)) * 16);
            asm volatile("cp.async.cg.shared.global [%0], [%1], 16;"
                         :: "r"(sA + off), "l"(gA + (size_t)row * KE + ls * 8));
        }
#pragma unroll
        for (int t = 0; t < BN / 16; t++) {
            int row = lr + t * 16;
            uint32_t off = row * 128 + ((ls ^ (row & 7)) * 16);
            asm volatile("cp.async.cg.shared.global [%0], [%1], 16;"
                         :: "r"(sB + off), "l"(gB + (size_t)row * KE + ls * 8));
        }
        asm volatile("cp.async.commit_group;");
    };

    issue(0);
    issue(1);

    const int lrow = lane & 15;
    const int lseg = lane >> 4;

    for (int ch = 0; ch < NCH; ++ch) {
        if (ch < NCH - 1) asm volatile("cp.async.wait_group 1;");
        else              asm volatile("cp.async.wait_group 0;");
        __syncthreads();
        if (ch + 2 < NCH) issue(ch + 2);

        const uint32_t sA = sbase + (ch % NSTAGE) * STAGE;
        const uint32_t sB = sA + STG_A;

#pragma unroll
        for (int k = 0; k < KC; k += 16) {
            const int seg = (k >> 3) + lseg;
            uint32_t ar[4][4];
#pragma unroll
            for (int mt = 0; mt < 4; mt++) {
                int row = wm + mt * 16 + lrow;
                uint32_t addr = sA + row * 128 + ((seg ^ (row & 7)) * 16);
                asm volatile("ldmatrix.sync.aligned.m8n8.x4.shared.b16 {%0,%1,%2,%3}, [%4];"
                             : "=r"(ar[mt][0]), "=r"(ar[mt][1]), "=r"(ar[mt][2]), "=r"(ar[mt][3])
                             : "r"(addr));
            }
            uint32_t br[NT / 2][4];
#pragma unroll
            for (int nt2 = 0; nt2 < NT / 2; nt2++) {
                int row = wn + nt2 * 16 + lrow;
                uint32_t addr = sB + row * 128 + ((seg ^ (row & 7)) * 16);
                asm volatile("ldmatrix.sync.aligned.m8n8.x4.shared.b16 {%0,%1,%2,%3}, [%4];"
                             : "=r"(br[nt2][0]), "=r"(br[nt2][1]), "=r"(br[nt2][2]), "=r"(br[nt2][3])
                             : "r"(addr));
            }
#pragma unroll
            for (int mt = 0; mt < 4; mt++)
#pragma unroll
                for (int nt = 0; nt < NT; nt++) {
                    uint32_t b0 = br[nt >> 1][nt & 1];
                    uint32_t b1 = br[nt >> 1][(nt & 1) + 2];
                    asm volatile(
                        "mma.sync.aligned.m16n8k16.row.col.f32.f16.f16.f32 "
                        "{%0,%1,%2,%3}, {%4,%5,%6,%7}, {%8,%9}, {%0,%1,%2,%3};"
                        : "+f"(acc[mt][nt][0]), "+f"(acc[mt][nt][1]),
                          "+f"(acc[mt][nt][2]), "+f"(acc[mt][nt][3])
                        : "r"(ar[mt][0]), "r"(ar[mt][1]), "r"(ar[mt][2]), "r"(ar[mt][3]),
                          "r"(b0), "r"(b1));
                }
        }
        __syncthreads();
    }

    const int r0 = bm + wm + (lane >> 2);
    const int c0 = bn + wn + (lane & 3) * 2;
#pragma unroll
    for (int nt = 0; nt < NT; nt++) {
        int col = c0 + nt * 8;
        float2 bb = *(const float2*)(bias + col);
#pragma unroll
        for (int mt = 0; mt < 4; mt++) {
            int row = r0 + mt * 16;
            float2 v0 = make_float2(acc[mt][nt][0] + bb.x, acc[mt][nt][1] + bb.y);
            float2 v1 = make_float2(acc[mt][nt][2] + bb.x, acc[mt][nt][3] + bb.y);
            if (HALFOUT) {
                *(__half2*)(Ch + (size_t)row * ldc + col) = __floats2half2_rn(v0.x, v0.y);
                *(__half2*)(Ch + (size_t)(row + 8) * ldc + col) = __floats2half2_rn(v1.x, v1.y);
            } else {
                *(float2*)(Cf + (size_t)row * ldc + col) = v0;
                *(float2*)(Cf + (size_t)(row + 8) * ldc + col) = v1;
            }
        }
    }
}

// ---------------------------------------------------------------------------
// Tensor-core attention. Q, K, V all fp16 from the fused QKVh buffer
// (stride 1536: Q at +0, K at +512, V at +1024). Structure identical to
// the passing R10 kernel except Q staging is a pure swizzled copy.
// Output -> Xe [hi|lo].
// ---------------------------------------------------------------------------
#define ATTN_SMEM (2 * MAXC * 128 + 8 * 2048)   // K 48K + V 48K + Q 16K = 112K

__device__ __forceinline__ void store_expanded(__half* Xe, int node, int col,
                                               float a, float b) {
    size_t row = (size_t)node * KE;
    __half ha = __float2half(a), hb = __float2half(b);
    __half la = __float2half(a - __half2float(ha));
    __half lb = __float2half(b - __half2float(hb));
    *(__half2*)(Xe + row + col) = __halves2half2(ha, hb);
    *(__half2*)(Xe + row + 512 + col) = __halves2half2(la, lb);
}

__global__ __launch_bounds__(256, 2) void attn_tc(
    const __half* __restrict__ QKVh, __half* __restrict__ Xe)
{
    extern __shared__ __align__(16) char smraw[];
    char* Kc = smraw;                     // [MAXC][128B]
    char* Vc = smraw + MAXC * 128;
    char* Qc = smraw + 2 * MAXC * 128;    // 8 warps x 2048B
    const uint32_t sK = smem_u32(Kc);
    const uint32_t sV = smem_u32(Vc);
    const uint32_t sQ = smem_u32(Qc);

    const int g = blockIdx.x, h = blockIdx.y;
    const int st = g_start[g];
    const int c = g_start[g + 1] - st;
    if (c <= 0) return;
    const int c16 = (c + 15) & ~15;
    const int nkt = c16 >> 4;
    const float fnpad = (float)(c16 - c);
    const int tid = threadIdx.x, wid = tid >> 5, lane = tid & 31;

    for (int idx = tid; idx < c16 * 8; idx += 256) {
        int r = idx >> 3, u = idx & 7;
        uint32_t off = r * 128 + ((u ^ (r & 7)) * 16);
        uint4 kv = make_uint4(0, 0, 0, 0), vv = make_uint4(0, 0, 0, 0);
        if (r < c) {
            const __half* src = QKVh + (size_t)(st + r) * 1536 + 512 + h * HDIM + u * 8;
            kv = *(const uint4*)src;
            vv = *(const uint4*)(src + 512);
        }
        *(uint4*)(Kc + off) = kv;
        *(uint4*)(Vc + off) = vv;
    }
    __syncthreads();

    const int lrow = lane & 15;
    const int lseg = lane >> 4;
    const int ntiles = (c + 15) >> 4;
    const uint32_t qb32 = sQ + wid * 2048;
    char* qbc = Qc + wid * 2048;
    const float scale = 0.125f;

    for (int qt = wid; qt < ntiles; qt += 8) {
        // stage this warp's 16x64 Q tile (fp16 copy, swizzled)
        for (int t = lane; t < 128; t += 32) {
            int row = t & 15, seg = t >> 4;
            int qrow = qt * 16 + row;
            if (qrow >= c) qrow = c - 1;
            uint4 pk = *(const uint4*)(QKVh + (size_t)(st + qrow) * 1536 + h * HDIM + seg * 8);
            *(uint4*)(qbc + row * 128 + ((seg ^ (row & 7)) * 16)) = pk;
        }
        __syncwarp();

        uint32_t aq[4][4];
#pragma unroll
        for (int ks = 0; ks < 4; ks++) {
            uint32_t addr = qb32 + lrow * 128 + (((ks * 2 + lseg) ^ (lrow & 7)) * 16);
            asm volatile("ldmatrix.sync.aligned.m8n8.x4.shared.b16 {%0,%1,%2,%3}, [%4];"
                         : "=r"(aq[ks][0]), "=r"(aq[ks][1]), "=r"(aq[ks][2]), "=r"(aq[ks][3])
                         : "r"(addr));
        }

        float oacc[8][4];
#pragma unroll
        for (int d = 0; d < 8; d++)
#pragma unroll
            for (int e = 0; e < 4; e++) oacc[d][e] = 0.f;
        float lr = 0.f, lr8 = 0.f;

        for (int kt = 0; kt < nkt; kt++) {
            const int krow = kt * 16 + lrow;
            float sacc[2][4];
#pragma unroll
            for (int nt = 0; nt < 2; nt++)
#pragma unroll
                for (int e = 0; e < 4; e++) sacc[nt][e] = 0.f;
#pragma unroll
            for (int ks = 0; ks < 4; ks++) {
                uint32_t addr = sK + krow * 128 + (((ks * 2 + lseg) ^ (krow & 7)) * 16);
                uint32_t bk[4];
                asm volatile("ldmatrix.sync.aligned.m8n8.x4.shared.b16 {%0,%1,%2,%3}, [%4];"
                             : "=r"(bk[0]), "=r"(bk[1]), "=r"(bk[2]), "=r"(bk[3])
                             : "r"(addr));
#pragma unroll
                for (int nt = 0; nt < 2; nt++) {
                    asm volatile(
                        "mma.sync.aligned.m16n8k16.row.col.f32.f16.f16.f32 "
                        "{%0,%1,%2,%3}, {%4,%5,%6,%7}, {%8,%9}, {%0,%1,%2,%3};"
                        : "+f"(sacc[nt][0]), "+f"(sacc[nt][1]),
                          "+f"(sacc[nt][2]), "+f"(sacc[nt][3])
                        : "r"(aq[ks][0]), "r"(aq[ks][1]), "r"(aq[ks][2]), "r"(aq[ks][3]),
                          "r"(bk[nt]), "r"(bk[nt + 2]));
                }
            }
            float p00 = __expf(fminf(sacc[0][0] * scale, 10.f));
            float p01 = __expf(fminf(sacc[0][1] * scale, 10.f));
            float p02 = __expf(fminf(sacc[0][2] * scale, 10.f));
            float p03 = __expf(fminf(sacc[0][3] * scale, 10.f));
            float p10 = __expf(fminf(sacc[1][0] * scale, 10.f));
            float p11 = __expf(fminf(sacc[1][1] * scale, 10.f));
            float p12 = __expf(fminf(sacc[1][2] * scale, 10.f));
            float p13 = __expf(fminf(sacc[1][3] * scale, 10.f));
            __half2 a0 = __floats2half2_rn(p00, p01);
            __half2 a1 = __floats2half2_rn(p02, p03);
            __half2 a2 = __floats2half2_rn(p10, p11);
            __half2 a3 = __floats2half2_rn(p12, p13);
            float2 f;
            f = __half22float2(a0); lr += f.x + f.y;
            f = __half22float2(a1); lr8 += f.x + f.y;
            f = __half22float2(a2); lr += f.x + f.y;
            f = __half22float2(a3); lr8 += f.x + f.y;
            uint32_t pa0 = *(uint32_t*)&a0, pa1 = *(uint32_t*)&a1;
            uint32_t pa2 = *(uint32_t*)&a2, pa3 = *(uint32_t*)&a3;

#pragma unroll
            for (int v16 = 0; v16 < 4; v16++) {
                uint32_t addr = sV + krow * 128 + (((v16 * 2 + lseg) ^ (krow & 7)) * 16);
                uint32_t bv[4];
                asm volatile("ldmatrix.sync.aligned.m8n8.x4.trans.shared.b16 {%0,%1,%2,%3}, [%4];"
                             : "=r"(bv[0]), "=r"(bv[1]), "=r"(bv[2]), "=r"(bv[3])
                             : "r"(addr));
                asm volatile(
                    "mma.sync.aligned.m16n8k16.row.col.f32.f16.f16.f32 "
                    "{%0,%1,%2,%3}, {%4,%5,%6,%7}, {%8,%9}, {%0,%1,%2,%3};"
                    : "+f"(oacc[v16 * 2][0]), "+f"(oacc[v16 * 2][1]),
                      "+f"(oacc[v16 * 2][2]), "+f"(oacc[v16 * 2][3])
                    : "r"(pa0), "r"(pa1), "r"(pa2), "r"(pa3),
                      "r"(bv[0]), "r"(bv[1]));
                asm volatile(
                    "mma.sync.aligned.m16n8k16.row.col.f32.f16.f16.f32 "
                    "{%0,%1,%2,%3}, {%4,%5,%6,%7}, {%8,%9}, {%0,%1,%2,%3};"
                    : "+f"(oacc[v16 * 2 + 1][0]), "+f"(oacc[v16 * 2 + 1][1]),
                      "+f"(oacc[v16 * 2 + 1][2]), "+f"(oacc[v16 * 2 + 1][3])
                    : "r"(pa0), "r"(pa1), "r"(pa2), "r"(pa3),
                      "r"(bv[2]), "r"(bv[3]));
            }
        }

        lr += __shfl_xor_sync(0xffffffffu, lr, 1);
        lr += __shfl_xor_sync(0xffffffffu, lr, 2);
        lr8 += __shfl_xor_sync(0xffffffffu, lr8, 1);
        lr8 += __shfl_xor_sync(0xffffffffu, lr8, 2);
        float inv = 1.f / (lr - fnpad);
        float inv8 = 1.f / (lr8 - fnpad);

        const int r0 = qt * 16 + (lane >> 2);
#pragma unroll
        for (int dt = 0; dt < 8; dt++) {
            int col = h * HDIM + dt * 8 + (lane & 3) * 2;
            if (r0 < c)
                store_expanded(Xe, st + r0, col, oacc[dt][0] * inv, oacc[dt][1] * inv);
            if (r0 + 8 < c)
                store_expanded(Xe, st + r0 + 8, col, oacc[dt][2] * inv8, oacc[dt][3] * inv8);
        }
    }
}

// ---------------------------------------------------------------------------
extern "C" void kernel_launch(void* const* d_in, const int* in_sizes, int n_in,
                              void* d_out, int out_size) {
    const float* x  = (const float*)d_in[0];
    const void*  bt = d_in[1];
    const float* wq = (const float*)d_in[2];
    const float* bq = (const float*)d_in[3];
    const float* wk = (const float*)d_in[4];
    const float* bk = (const float*)d_in[5];
    const float* wv = (const float*)d_in[6];
    const float* bv = (const float*)d_in[7];
    const float* wo = (const float*)d_in[8];
    const float* bo = (const float*)d_in[9];
    float* out = (float*)d_out;

    float* bcat;
    __half *QKVh, *Xe, *We;
    cudaGetSymbolAddress((void**)&QKVh, g_QKVh);
    cudaGetSymbolAddress((void**)&Xe, g_Xe);
    cudaGetSymbolAddress((void**)&We, g_We);
    cudaGetSymbolAddress((void**)&bcat, g_bcat);
    __half* Weo = We + 3 * (size_t)HID * KE;

    const int smem128 = NSTAGE * (16384 + 128 * 128);  // 98304
    const int smem64  = NSTAGE * (16384 + 64 * 128);   // 73728
    cudaFuncSetAttribute(gemm_hmma<128, 8, true>,
                         cudaFuncAttributeMaxDynamicSharedMemorySize, smem128);
    cudaFuncSetAttribute(gemm_hmma<64, 16, false>,
                         cudaFuncAttributeMaxDynamicSharedMemorySize, smem64);
    cudaFuncSetAttribute(attn_tc,
                         cudaFuncAttributeMaxDynamicSharedMemorySize, ATTN_SMEM);

    starts_kernel<<<(NNODES + 255) / 256, 256>>>(bt, NNODES);
    bias_cat<<<1, HID>>>(bq, bk, bv);

    const int xtot = NNODES * HID;
    expand_x<<<(xtot + 255) / 256, 256>>>(x, Xe, xtot);
    expand_w4<<<(4 * HID * HID + 255) / 256, 256>>>(wq, wk, wv, wo, We);

    // fused Q|K|V projection: N = 1536, K = 512 (hi(x) only), all fp16 out
    gemm_hmma<128, 8, true><<<dim3(12, 80), 128, smem128>>>(
        Xe, We, bcat, nullptr, QKVh, 1536);

    // tensor-core attention; writes O in expanded [hi|lo] form into Xe
    attn_tc<<<dim3(NGRAPH, HEADS), 256, ATTN_SMEM>>>(QKVh, Xe);

    // output projection: K = 1024 over O's [hi|lo], fp32 out
    gemm_hmma<64, 16, false><<<dim3(8, 80), 128, smem64>>>(
        Xe, Weo, bo, out, nullptr, 512);
}

// round 12
// speedup vs baseline: 7.4265x; 1.1618x over previous
#include <cuda_runtime.h>
#include <cuda_fp16.h>
#include <cstdint>

#define NNODES 10240
#define NGRAPH 64
#define HID 512
#define HEADS 8
#define HDIM 64
#define MAXC 384

#define KC 64                // halves per K-chunk (128B per row)
#define NCH 8                // K = 512 everywhere
#define NSTAGE 3

// ---------------------------------------------------------------------------
// Scratch (device globals: no allocation allowed)
// ---------------------------------------------------------------------------
__device__ __align__(16) __half g_QKVh[(size_t)NNODES * 1536];    // Q|K|V fp16
__device__ __align__(16) __half g_Xh[(size_t)NNODES * HID];       // x hi / O fp16
__device__ __align__(16) __half g_Wh[4][(size_t)HID * HID];       // wq,wk,wv,wo fp16
__device__ float g_bcat[3 * HID];
__device__ int g_start[NGRAPH + 2];

// ---------------------------------------------------------------------------
__device__ __forceinline__ uint32_t smem_u32(const void* p) {
    uint32_t a;
    asm("{ .reg .u64 t; cvta.to.shared.u64 t, %1; cvt.u32.u64 %0, t; }" : "=r"(a) : "l"(p));
    return a;
}

// ---------------------------------------------------------------------------
// Segment starts from sorted batch (int32 or int64 storage).
// ---------------------------------------------------------------------------
__global__ void starts_kernel(const void* bptr, int n) {
    const int* b32 = (const int*)bptr;
    const long long* b64 = (const long long*)bptr;
    const bool is64 = (b32[n - 1] == 0);
    int i = blockIdx.x * blockDim.x + threadIdx.x;
    if (i >= n) return;
    int bi = is64 ? (int)b64[i] : b32[i];
    int bp = (i == 0) ? -1 : (is64 ? (int)b64[i - 1] : b32[i - 1]);
    for (int g = bp + 1; g <= bi; ++g) g_start[g] = i;
    if (i == n - 1)
        for (int g = bi + 1; g <= NGRAPH; ++g) g_start[g] = n;
}

__global__ void bias_cat(const float* bq, const float* bk, const float* bv) {
    int i = threadIdx.x;
    g_bcat[i] = bq[i];
    g_bcat[HID + i] = bk[i];
    g_bcat[2 * HID + i] = bv[i];
}

// ---------------------------------------------------------------------------
// fp32 -> fp16 (hi only).
// ---------------------------------------------------------------------------
__global__ void expand_x(const float* __restrict__ X, __half* __restrict__ Xh, int total) {
    int i = blockIdx.x * blockDim.x + threadIdx.x;
    if (i >= total) return;
    Xh[i] = __float2half(X[i]);
}

__global__ void expand_w4(const float* __restrict__ w0, const float* __restrict__ w1,
                          const float* __restrict__ w2, const float* __restrict__ w3,
                          __half* __restrict__ Wh) {
    int i = blockIdx.x * blockDim.x + threadIdx.x;
    if (i >= 4 * HID * HID) return;
    int m = i >> 18;
    int local = i & 262143;
    const float* W = (m == 0) ? w0 : (m == 1) ? w1 : (m == 2) ? w2 : w3;
    Wh[i] = __float2half(W[local]);
}

// ---------------------------------------------------------------------------
// HMMA GEMM: C[M, N] = A[M,512](fp16) * B[N,512](fp16)^T + bias.
// 128 x BN CTA tile, 4 warps (2m x 2n), warp tile 64 x BN/2,
// mma.sync.m16n8k16, XOR-swizzled smem, 3-stage cp.async ring, K = 512.
// HALFOUT -> fp16 stores (ldc), else fp32 (ldc).
// ---------------------------------------------------------------------------
template <int BN, bool HALFOUT>
__global__ __launch_bounds__(128, 2) void gemm_hmma(
    const __half* __restrict__ A, const __half* __restrict__ B,
    const float* __restrict__ bias, float* __restrict__ Cf,
    __half* __restrict__ Ch, int ldc)
{
    constexpr int NT = BN / 16;            // n-subtiles (8 cols) per warp
    constexpr int STG_A = 16384;
    constexpr int STG_B = BN * 128;
    constexpr int STAGE = STG_A + STG_B;

    extern __shared__ char sm_raw[];
    const int tid = threadIdx.x;
    const int wid = tid >> 5, lane = tid & 31;
    const int bm = blockIdx.y * 128, bn = blockIdx.x * BN;
    const int wm = (wid & 1) * 64;
    const int wn = (wid >> 1) * (BN / 2);
    const uint32_t sbase = smem_u32(sm_raw);

    float acc[4][NT][4];
#pragma unroll
    for (int a = 0; a < 4; a++)
#pragma unroll
        for (int b = 0; b < NT; b++)
#pragma unroll
            for (int c = 0; c < 4; c++) acc[a][b][c] = 0.f;

    const int lr = tid >> 3;      // 0..15 row group
    const int ls = tid & 7;       // 0..7 16B segment

    auto issue = [&](int ch) {
        const __half* gA = A + (size_t)bm * HID + ch * KC;
        const __half* gB = B + (size_t)bn * HID + ch * KC;
        uint32_t sA = sbase + (ch % NSTAGE) * STAGE;
        uint32_t sB = sA + STG_A;
#pragma unroll
        for (int t = 0; t < 8; t++) {
            int row = lr + t * 16;
            uint32_t off = row * 128 + ((ls ^ (row & 7)) * 16);
            asm volatile("cp.async.cg.shared.global [%0], [%1], 16;"
                         :: "r"(sA + off), "l"(gA + (size_t)row * HID + ls * 8));
        }
#pragma unroll
        for (int t = 0; t < BN / 16; t++) {
            int row = lr + t * 16;
            uint32_t off = row * 128 + ((ls ^ (row & 7)) * 16);
            asm volatile("cp.async.cg.shared.global [%0], [%1], 16;"
                         :: "r"(sB + off), "l"(gB + (size_t)row * HID + ls * 8));
        }
        asm volatile("cp.async.commit_group;");
    };

    issue(0);
    issue(1);

    const int lrow = lane & 15;
    const int lseg = lane >> 4;

    for (int ch = 0; ch < NCH; ++ch) {
        if (ch < NCH - 1) asm volatile("cp.async.wait_group 1;");
        else              asm volatile("cp.async.wait_group 0;");
        __syncthreads();
        if (ch + 2 < NCH) issue(ch + 2);

        const uint32_t sA = sbase + (ch % NSTAGE) * STAGE;
        const uint32_t sB = sA + STG_A;

#pragma unroll
        for (int k = 0; k < KC; k += 16) {
            const int seg = (k >> 3) + lseg;
            uint32_t ar[4][4];
#pragma unroll
            for (int mt = 0; mt < 4; mt++) {
                int row = wm + mt * 16 + lrow;
                uint32_t addr = sA + row * 128 + ((seg ^ (row & 7)) * 16);
                asm volatile("ldmatrix.sync.aligned.m8n8.x4.shared.b16 {%0,%1,%2,%3}, [%4];"
                             : "=r"(ar[mt][0]), "=r"(ar[mt][1]), "=r"(ar[mt][2]), "=r"(ar[mt][3])
                             : "r"(addr));
            }
            uint32_t br[NT / 2][4];
#pragma unroll
            for (int nt2 = 0; nt2 < NT / 2; nt2++) {
                int row = wn + nt2 * 16 + lrow;
                uint32_t addr = sB + row * 128 + ((seg ^ (row & 7)) * 16);
                asm volatile("ldmatrix.sync.aligned.m8n8.x4.shared.b16 {%0,%1,%2,%3}, [%4];"
                             : "=r"(br[nt2][0]), "=r"(br[nt2][1]), "=r"(br[nt2][2]), "=r"(br[nt2][3])
                             : "r"(addr));
            }
#pragma unroll
            for (int mt = 0; mt < 4; mt++)
#pragma unroll
                for (int nt = 0; nt < NT; nt++) {
                    uint32_t b0 = br[nt >> 1][nt & 1];
                    uint32_t b1 = br[nt >> 1][(nt & 1) + 2];
                    asm volatile(
                        "mma.sync.aligned.m16n8k16.row.col.f32.f16.f16.f32 "
                        "{%0,%1,%2,%3}, {%4,%5,%6,%7}, {%8,%9}, {%0,%1,%2,%3};"
                        : "+f"(acc[mt][nt][0]), "+f"(acc[mt][nt][1]),
                          "+f"(acc[mt][nt][2]), "+f"(acc[mt][nt][3])
                        : "r"(ar[mt][0]), "r"(ar[mt][1]), "r"(ar[mt][2]), "r"(ar[mt][3]),
                          "r"(b0), "r"(b1));
                }
        }
        __syncthreads();
    }

    const int r0 = bm + wm + (lane >> 2);
    const int c0 = bn + wn + (lane & 3) * 2;
#pragma unroll
    for (int nt = 0; nt < NT; nt++) {
        int col = c0 + nt * 8;
        float2 bb = *(const float2*)(bias + col);
#pragma unroll
        for (int mt = 0; mt < 4; mt++) {
            int row = r0 + mt * 16;
            float2 v0 = make_float2(acc[mt][nt][0] + bb.x, acc[mt][nt][1] + bb.y);
            float2 v1 = make_float2(acc[mt][nt][2] + bb.x, acc[mt][nt][3] + bb.y);
            if (HALFOUT) {
                *(__half2*)(Ch + (size_t)row * ldc + col) = __floats2half2_rn(v0.x, v0.y);
                *(__half2*)(Ch + (size_t)(row + 8) * ldc + col) = __floats2half2_rn(v1.x, v1.y);
            } else {
                *(float2*)(Cf + (size_t)row * ldc + col) = v0;
                *(float2*)(Cf + (size_t)(row + 8) * ldc + col) = v1;
            }
        }
    }
}

// ---------------------------------------------------------------------------
// Tensor-core attention. Q, K, V fp16 from fused QKVh (stride 1536).
// Output O -> g_Xh as plain fp16 (stride 512).
// ---------------------------------------------------------------------------
#define ATTN_SMEM (2 * MAXC * 128 + 8 * 2048)   // K 48K + V 48K + Q 16K = 112K

__global__ __launch_bounds__(256, 2) void attn_tc(
    const __half* __restrict__ QKVh, __half* __restrict__ Oh)
{
    extern __shared__ __align__(16) char smraw[];
    char* Kc = smraw;                     // [MAXC][128B]
    char* Vc = smraw + MAXC * 128;
    char* Qc = smraw + 2 * MAXC * 128;    // 8 warps x 2048B
    const uint32_t sK = smem_u32(Kc);
    const uint32_t sV = smem_u32(Vc);
    const uint32_t sQ = smem_u32(Qc);

    const int g = blockIdx.x, h = blockIdx.y;
    const int st = g_start[g];
    const int c = g_start[g + 1] - st;
    if (c <= 0) return;
    const int c16 = (c + 15) & ~15;
    const int nkt = c16 >> 4;
    const float fnpad = (float)(c16 - c);
    const int tid = threadIdx.x, wid = tid >> 5, lane = tid & 31;

    for (int idx = tid; idx < c16 * 8; idx += 256) {
        int r = idx >> 3, u = idx & 7;
        uint32_t off = r * 128 + ((u ^ (r & 7)) * 16);
        uint4 kv = make_uint4(0, 0, 0, 0), vv = make_uint4(0, 0, 0, 0);
        if (r < c) {
            const __half* src = QKVh + (size_t)(st + r) * 1536 + 512 + h * HDIM + u * 8;
            kv = *(const uint4*)src;
            vv = *(const uint4*)(src + 512);
        }
        *(uint4*)(Kc + off) = kv;
        *(uint4*)(Vc + off) = vv;
    }
    __syncthreads();

    const int lrow = lane & 15;
    const int lseg = lane >> 4;
    const int ntiles = (c + 15) >> 4;
    const uint32_t qb32 = sQ + wid * 2048;
    char* qbc = Qc + wid * 2048;
    const float scale = 0.125f;

    for (int qt = wid; qt < ntiles; qt += 8) {
        for (int t = lane; t < 128; t += 32) {
            int row = t & 15, seg = t >> 4;
            int qrow = qt * 16 + row;
            if (qrow >= c) qrow = c - 1;
            uint4 pk = *(const uint4*)(QKVh + (size_t)(st + qrow) * 1536 + h * HDIM + seg * 8);
            *(uint4*)(qbc + row * 128 + ((seg ^ (row & 7)) * 16)) = pk;
        }
        __syncwarp();

        uint32_t aq[4][4];
#pragma unroll
        for (int ks = 0; ks < 4; ks++) {
            uint32_t addr = qb32 + lrow * 128 + (((ks * 2 + lseg) ^ (lrow & 7)) * 16);
            asm volatile("ldmatrix.sync.aligned.m8n8.x4.shared.b16 {%0,%1,%2,%3}, [%4];"
                         : "=r"(aq[ks][0]), "=r"(aq[ks][1]), "=r"(aq[ks][2]), "=r"(aq[ks][3])
                         : "r"(addr));
        }

        float oacc[8][4];
#pragma unroll
        for (int d = 0; d < 8; d++)
#pragma unroll
            for (int e = 0; e < 4; e++) oacc[d][e] = 0.f;
        float lr = 0.f, lr8 = 0.f;

        for (int kt = 0; kt < nkt; kt++) {
            const int krow = kt * 16 + lrow;
            float sacc[2][4];
#pragma unroll
            for (int nt = 0; nt < 2; nt++)
#pragma unroll
                for (int e = 0; e < 4; e++) sacc[nt][e] = 0.f;
#pragma unroll
            for (int ks = 0; ks < 4; ks++) {
                uint32_t addr = sK + krow * 128 + (((ks * 2 + lseg) ^ (krow & 7)) * 16);
                uint32_t bk[4];
                asm volatile("ldmatrix.sync.aligned.m8n8.x4.shared.b16 {%0,%1,%2,%3}, [%4];"
                             : "=r"(bk[0]), "=r"(bk[1]), "=r"(bk[2]), "=r"(bk[3])
                             : "r"(addr));
#pragma unroll
                for (int nt = 0; nt < 2; nt++) {
                    asm volatile(
                        "mma.sync.aligned.m16n8k16.row.col.f32.f16.f16.f32 "
                        "{%0,%1,%2,%3}, {%4,%5,%6,%7}, {%8,%9}, {%0,%1,%2,%3};"
                        : "+f"(sacc[nt][0]), "+f"(sacc[nt][1]),
                          "+f"(sacc[nt][2]), "+f"(sacc[nt][3])
                        : "r"(aq[ks][0]), "r"(aq[ks][1]), "r"(aq[ks][2]), "r"(aq[ks][3]),
                          "r"(bk[nt]), "r"(bk[nt + 2]));
                }
            }
            float p00 = __expf(fminf(sacc[0][0] * scale, 10.f));
            float p01 = __expf(fminf(sacc[0][1] * scale, 10.f));
            float p02 = __expf(fminf(sacc[0][2] * scale, 10.f));
            float p03 = __expf(fminf(sacc[0][3] * scale, 10.f));
            float p10 = __expf(fminf(sacc[1][0] * scale, 10.f));
            float p11 = __expf(fminf(sacc[1][1] * scale, 10.f));
            float p12 = __expf(fminf(sacc[1][2] * scale, 10.f));
            float p13 = __expf(fminf(sacc[1][3] * scale, 10.f));
            __half2 a0 = __floats2half2_rn(p00, p01);
            __half2 a1 = __floats2half2_rn(p02, p03);
            __half2 a2 = __floats2half2_rn(p10, p11);
            __half2 a3 = __floats2half2_rn(p12, p13);
            float2 f;
            f = __half22float2(a0); lr += f.x + f.y;
            f = __half22float2(a1); lr8 += f.x + f.y;
            f = __half22float2(a2); lr += f.x + f.y;
            f = __half22float2(a3); lr8 += f.x + f.y;
            uint32_t pa0 = *(uint32_t*)&a0, pa1 = *(uint32_t*)&a1;
            uint32_t pa2 = *(uint32_t*)&a2, pa3 = *(uint32_t*)&a3;

#pragma unroll
            for (int v16 = 0; v16 < 4; v16++) {
                uint32_t addr = sV + krow * 128 + (((v16 * 2 + lseg) ^ (krow & 7)) * 16);
                uint32_t bv[4];
                asm volatile("ldmatrix.sync.aligned.m8n8.x4.trans.shared.b16 {%0,%1,%2,%3}, [%4];"
                             : "=r"(bv[0]), "=r"(bv[1]), "=r"(bv[2]), "=r"(bv[3])
                             : "r"(addr));
                asm volatile(
                    "mma.sync.aligned.m16n8k16.row.col.f32.f16.f16.f32 "
                    "{%0,%1,%2,%3}, {%4,%5,%6,%7}, {%8,%9}, {%0,%1,%2,%3};"
                    : "+f"(oacc[v16 * 2][0]), "+f"(oacc[v16 * 2][1]),
                      "+f"(oacc[v16 * 2][2]), "+f"(oacc[v16 * 2][3])
                    : "r"(pa0), "r"(pa1), "r"(pa2), "r"(pa3),
                      "r"(bv[0]), "r"(bv[1]));
                asm volatile(
                    "mma.sync.aligned.m16n8k16.row.col.f32.f16.f16.f32 "
                    "{%0,%1,%2,%3}, {%4,%5,%6,%7}, {%8,%9}, {%0,%1,%2,%3};"
                    : "+f"(oacc[v16 * 2 + 1][0]), "+f"(oacc[v16 * 2 + 1][1]),
                      "+f"(oacc[v16 * 2 + 1][2]), "+f"(oacc[v16 * 2 + 1][3])
                    : "r"(pa0), "r"(pa1), "r"(pa2), "r"(pa3),
                      "r"(bv[2]), "r"(bv[3]));
            }
        }

        lr += __shfl_xor_sync(0xffffffffu, lr, 1);
        lr += __shfl_xor_sync(0xffffffffu, lr, 2);
        lr8 += __shfl_xor_sync(0xffffffffu, lr8, 1);
        lr8 += __shfl_xor_sync(0xffffffffu, lr8, 2);
        float inv = 1.f / (lr - fnpad);
        float inv8 = 1.f / (lr8 - fnpad);

        const int r0 = qt * 16 + (lane >> 2);
#pragma unroll
        for (int dt = 0; dt < 8; dt++) {
            int col = h * HDIM + dt * 8 + (lane & 3) * 2;
            if (r0 < c)
                *(__half2*)(Oh + (size_t)(st + r0) * HID + col) =
                    __floats2half2_rn(oacc[dt][0] * inv, oacc[dt][1] * inv);
            if (r0 + 8 < c)
                *(__half2*)(Oh + (size_t)(st + r0 + 8) * HID + col) =
                    __floats2half2_rn(oacc[dt][2] * inv8, oacc[dt][3] * inv8);
        }
    }
}

// ---------------------------------------------------------------------------
extern "C" void kernel_launch(void* const* d_in, const int* in_sizes, int n_in,
                              void* d_out, int out_size) {
    const float* x  = (const float*)d_in[0];
    const void*  bt = d_in[1];
    const float* wq = (const float*)d_in[2];
    const float* bq = (const float*)d_in[3];
    const float* wk = (const float*)d_in[4];
    const float* bk = (const float*)d_in[5];
    const float* wv = (const float*)d_in[6];
    const float* bv = (const float*)d_in[7];
    const float* wo = (const float*)d_in[8];
    const float* bo = (const float*)d_in[9];
    float* out = (float*)d_out;

    float* bcat;
    __half *QKVh, *Xh, *Wh;
    cudaGetSymbolAddress((void**)&QKVh, g_QKVh);
    cudaGetSymbolAddress((void**)&Xh, g_Xh);
    cudaGetSymbolAddress((void**)&Wh, g_Wh);
    cudaGetSymbolAddress((void**)&bcat, g_bcat);
    __half* Who = Wh + 3 * (size_t)HID * HID;

    const int smem128 = NSTAGE * (16384 + 128 * 128);  // 98304
    const int smem64  = NSTAGE * (16384 + 64 * 128);   // 73728
    cudaFuncSetAttribute(gemm_hmma<128, true>,
                         cudaFuncAttributeMaxDynamicSharedMemorySize, smem128);
    cudaFuncSetAttribute(gemm_hmma<64, false>,
                         cudaFuncAttributeMaxDynamicSharedMemorySize, smem64);
    cudaFuncSetAttribute(attn_tc,
                         cudaFuncAttributeMaxDynamicSharedMemorySize, ATTN_SMEM);

    starts_kernel<<<(NNODES + 255) / 256, 256>>>(bt, NNODES);
    bias_cat<<<1, HID>>>(bq, bk, bv);

    const int xtot = NNODES * HID;
    expand_x<<<(xtot + 255) / 256, 256>>>(x, Xh, xtot);
    expand_w4<<<(4 * HID * HID + 255) / 256, 256>>>(wq, wk, wv, wo, Wh);

    // fused Q|K|V projection: N = 1536, K = 512, fp16 out
    gemm_hmma<128, true><<<dim3(12, 80), 128, smem128>>>(
        Xh, Wh, bcat, nullptr, QKVh, 1536);

    // tensor-core attention; O -> Xh (fp16)
    attn_tc<<<dim3(NGRAPH, HEADS), 256, ATTN_SMEM>>>(QKVh, Xh);

    // output projection: K = 512, fp32 out
    gemm_hmma<64, false><<<dim3(8, 80), 128, smem64>>>(
        Xh, Who, bo, out, nullptr, 512);
}

// round 13
// speedup vs baseline: 7.8849x; 1.0617x over previous
#include <cuda_runtime.h>
#include <cuda_fp16.h>
#include <cstdint>

#define NNODES 10240
#define NGRAPH 64
#define HID 512
#define HEADS 8
#define HDIM 64
#define MAXC 384

#define KC 64                // halves per K-chunk (128B per row)
#define NCH 8                // K = 512 everywhere
#define NSTAGE 3

// ---------------------------------------------------------------------------
// Scratch (device globals: no allocation allowed)
// ---------------------------------------------------------------------------
__device__ __align__(16) __half g_QKVh[(size_t)NNODES * 1536];    // Q|K|V fp16
__device__ __align__(16) __half g_Xh[(size_t)NNODES * HID];       // x hi / O fp16
__device__ __align__(16) __half g_Wh[4][(size_t)HID * HID];       // wq,wk,wv,wo fp16
__device__ float g_bcat[3 * HID];
__device__ int g_start[NGRAPH + 2];

// ---------------------------------------------------------------------------
__device__ __forceinline__ uint32_t smem_u32(const void* p) {
    uint32_t a;
    asm("{ .reg .u64 t; cvta.to.shared.u64 t, %1; cvt.u32.u64 %0, t; }" : "=r"(a) : "l"(p));
    return a;
}

// ---------------------------------------------------------------------------
// Fused prep: one launch does W fp16-convert, x fp16-convert, segment starts,
// and bias concat, as disjoint ranges of a flat grid.
// ---------------------------------------------------------------------------
#define PREP_W   (4 * HID * HID)            // 1048576
#define PREP_X   (NNODES * HID)             // 5242880
#define PREP_TOT (PREP_W + PREP_X + NNODES + HID)

__global__ void prep_kernel(
    const float* __restrict__ X, const void* bptr,
    const float* __restrict__ w0, const float* __restrict__ w1,
    const float* __restrict__ w2, const float* __restrict__ w3,
    const float* __restrict__ bq, const float* __restrict__ bk,
    const float* __restrict__ bv,
    __half* __restrict__ Xh, __half* __restrict__ Wh)
{
    int i = blockIdx.x * blockDim.x + threadIdx.x;
    if (i < PREP_W) {
        int m = i >> 18;
        int local = i & 262143;
        const float* W = (m == 0) ? w0 : (m == 1) ? w1 : (m == 2) ? w2 : w3;
        Wh[i] = __float2half(W[local]);
    } else if (i < PREP_W + PREP_X) {
        int j = i - PREP_W;
        Xh[j] = __float2half(X[j]);
    } else if (i < PREP_W + PREP_X + NNODES) {
        int j = i - PREP_W - PREP_X;
        const int* b32 = (const int*)bptr;
        const long long* b64 = (const long long*)bptr;
        const bool is64 = (b32[NNODES - 1] == 0);
        int bi = is64 ? (int)b64[j] : b32[j];
        int bp = (j == 0) ? -1 : (is64 ? (int)b64[j - 1] : b32[j - 1]);
        for (int g = bp + 1; g <= bi; ++g) g_start[g] = j;
        if (j == NNODES - 1)
            for (int g = bi + 1; g <= NGRAPH; ++g) g_start[g] = NNODES;
    } else if (i < PREP_TOT) {
        int j = i - PREP_W - PREP_X - NNODES;
        g_bcat[j] = bq[j];
        g_bcat[HID + j] = bk[j];
        g_bcat[2 * HID + j] = bv[j];
    }
}

// ---------------------------------------------------------------------------
// HMMA GEMM: C[M, N] = A[M,512](fp16) * B[N,512](fp16)^T + bias.
// 128 x BN CTA tile, 4 warps (2m x 2n), warp tile 64 x BN/2,
// mma.sync.m16n8k16, XOR-swizzled smem, 3-stage cp.async ring, K = 512.
// ONE barrier per chunk (top wait+sync also orders buffer reuse: at iter
// ch+1 all warps have finished iter-ch reads of stage ch%3 before issue
// overwrites it). HALFOUT -> fp16 stores (ldc), else fp32 (ldc).
// ---------------------------------------------------------------------------
template <int BN, bool HALFOUT>
__global__ __launch_bounds__(128, 2) void gemm_hmma(
    const __half* __restrict__ A, const __half* __restrict__ B,
    const float* __restrict__ bias, float* __restrict__ Cf,
    __half* __restrict__ Ch, int ldc)
{
    constexpr int NT = BN / 16;            // n-subtiles (8 cols) per warp
    constexpr int STG_A = 16384;
    constexpr int STG_B = BN * 128;
    constexpr int STAGE = STG_A + STG_B;

    extern __shared__ char sm_raw[];
    const int tid = threadIdx.x;
    const int wid = tid >> 5, lane = tid & 31;
    const int bm = blockIdx.y * 128, bn = blockIdx.x * BN;
    const int wm = (wid & 1) * 64;
    const int wn = (wid >> 1) * (BN / 2);
    const uint32_t sbase = smem_u32(sm_raw);

    float acc[4][NT][4];
#pragma unroll
    for (int a = 0; a < 4; a++)
#pragma unroll
        for (int b = 0; b < NT; b++)
#pragma unroll
            for (int c = 0; c < 4; c++) acc[a][b][c] = 0.f;

    const int lr = tid >> 3;      // 0..15 row group
    const int ls = tid & 7;       // 0..7 16B segment

    auto issue = [&](int ch) {
        const __half* gA = A + (size_t)bm * HID + ch * KC;
        const __half* gB = B + (size_t)bn * HID + ch * KC;
        uint32_t sA = sbase + (ch % NSTAGE) * STAGE;
        uint32_t sB = sA + STG_A;
#pragma unroll
        for (int t = 0; t < 8; t++) {
            int row = lr + t * 16;
            uint32_t off = row * 128 + ((ls ^ (row & 7)) * 16);
            asm volatile("cp.async.cg.shared.global [%0], [%1], 16;"
                         :: "r"(sA + off), "l"(gA + (size_t)row * HID + ls * 8));
        }
#pragma unroll
        for (int t = 0; t < BN / 16; t++) {
            int row = lr + t * 16;
            uint32_t off = row * 128 + ((ls ^ (row & 7)) * 16);
            asm volatile("cp.async.cg.shared.global [%0], [%1], 16;"
                         :: "r"(sB + off), "l"(gB + (size_t)row * HID + ls * 8));
        }
        asm volatile("cp.async.commit_group;");
    };

    issue(0);
    issue(1);

    const int lrow = lane & 15;
    const int lseg = lane >> 4;

    for (int ch = 0; ch < NCH; ++ch) {
        if (ch < NCH - 1) asm volatile("cp.async.wait_group 1;");
        else              asm volatile("cp.async.wait_group 0;");
        __syncthreads();
        if (ch + 2 < NCH) issue(ch + 2);

        const uint32_t sA = sbase + (ch % NSTAGE) * STAGE;
        const uint32_t sB = sA + STG_A;

#pragma unroll
        for (int k = 0; k < KC; k += 16) {
            const int seg = (k >> 3) + lseg;
            uint32_t ar[4][4];
#pragma unroll
            for (int mt = 0; mt < 4; mt++) {
                int row = wm + mt * 16 + lrow;
                uint32_t addr = sA + row * 128 + ((seg ^ (row & 7)) * 16);
                asm volatile("ldmatrix.sync.aligned.m8n8.x4.shared.b16 {%0,%1,%2,%3}, [%4];"
                             : "=r"(ar[mt][0]), "=r"(ar[mt][1]), "=r"(ar[mt][2]), "=r"(ar[mt][3])
                             : "r"(addr));
            }
            uint32_t br[NT / 2][4];
#pragma unroll
            for (int nt2 = 0; nt2 < NT / 2; nt2++) {
                int row = wn + nt2 * 16 + lrow;
                uint32_t addr = sB + row * 128 + ((seg ^ (row & 7)) * 16);
                asm volatile("ldmatrix.sync.aligned.m8n8.x4.shared.b16 {%0,%1,%2,%3}, [%4];"
                             : "=r"(br[nt2][0]), "=r"(br[nt2][1]), "=r"(br[nt2][2]), "=r"(br[nt2][3])
                             : "r"(addr));
            }
#pragma unroll
            for (int mt = 0; mt < 4; mt++)
#pragma unroll
                for (int nt = 0; nt < NT; nt++) {
                    uint32_t b0 = br[nt >> 1][nt & 1];
                    uint32_t b1 = br[nt >> 1][(nt & 1) + 2];
                    asm volatile(
                        "mma.sync.aligned.m16n8k16.row.col.f32.f16.f16.f32 "
                        "{%0,%1,%2,%3}, {%4,%5,%6,%7}, {%8,%9}, {%0,%1,%2,%3};"
                        : "+f"(acc[mt][nt][0]), "+f"(acc[mt][nt][1]),
                          "+f"(acc[mt][nt][2]), "+f"(acc[mt][nt][3])
                        : "r"(ar[mt][0]), "r"(ar[mt][1]), "r"(ar[mt][2]), "r"(ar[mt][3]),
                          "r"(b0), "r"(b1));
                }
        }
        // no bottom barrier: next iteration's top wait+sync orders reuse
    }

    const int r0 = bm + wm + (lane >> 2);
    const int c0 = bn + wn + (lane & 3) * 2;
#pragma unroll
    for (int nt = 0; nt < NT; nt++) {
        int col = c0 + nt * 8;
        float2 bb = *(const float2*)(bias + col);
#pragma unroll
        for (int mt = 0; mt < 4; mt++) {
            int row = r0 + mt * 16;
            float2 v0 = make_float2(acc[mt][nt][0] + bb.x, acc[mt][nt][1] + bb.y);
            float2 v1 = make_float2(acc[mt][nt][2] + bb.x, acc[mt][nt][3] + bb.y);
            if (HALFOUT) {
                *(__half2*)(Ch + (size_t)row * ldc + col) = __floats2half2_rn(v0.x, v0.y);
                *(__half2*)(Ch + (size_t)(row + 8) * ldc + col) = __floats2half2_rn(v1.x, v1.y);
            } else {
                *(float2*)(Cf + (size_t)row * ldc + col) = v0;
                *(float2*)(Cf + (size_t)(row + 8) * ldc + col) = v1;
            }
        }
    }
}

// ---------------------------------------------------------------------------
// Tensor-core attention (unchanged from passing R12 kernel).
// Q, K, V fp16 from fused QKVh (stride 1536). O -> g_Xh fp16 (stride 512).
// ---------------------------------------------------------------------------
#define ATTN_SMEM (2 * MAXC * 128 + 8 * 2048)   // K 48K + V 48K + Q 16K = 112K

__global__ __launch_bounds__(256, 2) void attn_tc(
    const __half* __restrict__ QKVh, __half* __restrict__ Oh)
{
    extern __shared__ __align__(16) char smraw[];
    char* Kc = smraw;                     // [MAXC][128B]
    char* Vc = smraw + MAXC * 128;
    char* Qc = smraw + 2 * MAXC * 128;    // 8 warps x 2048B
    const uint32_t sK = smem_u32(Kc);
    const uint32_t sV = smem_u32(Vc);
    const uint32_t sQ = smem_u32(Qc);

    const int g = blockIdx.x, h = blockIdx.y;
    const int st = g_start[g];
    const int c = g_start[g + 1] - st;
    if (c <= 0) return;
    const int c16 = (c + 15) & ~15;
    const int nkt = c16 >> 4;
    const float fnpad = (float)(c16 - c);
    const int tid = threadIdx.x, wid = tid >> 5, lane = tid & 31;

    for (int idx = tid; idx < c16 * 8; idx += 256) {
        int r = idx >> 3, u = idx & 7;
        uint32_t off = r * 128 + ((u ^ (r & 7)) * 16);
        uint4 kv = make_uint4(0, 0, 0, 0), vv = make_uint4(0, 0, 0, 0);
        if (r < c) {
            const __half* src = QKVh + (size_t)(st + r) * 1536 + 512 + h * HDIM + u * 8;
            kv = *(const uint4*)src;
            vv = *(const uint4*)(src + 512);
        }
        *(uint4*)(Kc + off) = kv;
        *(uint4*)(Vc + off) = vv;
    }
    __syncthreads();

    const int lrow = lane & 15;
    const int lseg = lane >> 4;
    const int ntiles = (c + 15) >> 4;
    const uint32_t qb32 = sQ + wid * 2048;
    char* qbc = Qc + wid * 2048;
    const float scale = 0.125f;

    for (int qt = wid; qt < ntiles; qt += 8) {
        for (int t = lane; t < 128; t += 32) {
            int row = t & 15, seg = t >> 4;
            int qrow = qt * 16 + row;
            if (qrow >= c) qrow = c - 1;
            uint4 pk = *(const uint4*)(QKVh + (size_t)(st + qrow) * 1536 + h * HDIM + seg * 8);
            *(uint4*)(qbc + row * 128 + ((seg ^ (row & 7)) * 16)) = pk;
        }
        __syncwarp();

        uint32_t aq[4][4];
#pragma unroll
        for (int ks = 0; ks < 4; ks++) {
            uint32_t addr = qb32 + lrow * 128 + (((ks * 2 + lseg) ^ (lrow & 7)) * 16);
            asm volatile("ldmatrix.sync.aligned.m8n8.x4.shared.b16 {%0,%1,%2,%3}, [%4];"
                         : "=r"(aq[ks][0]), "=r"(aq[ks][1]), "=r"(aq[ks][2]), "=r"(aq[ks][3])
                         : "r"(addr));
        }

        float oacc[8][4];
#pragma unroll
        for (int d = 0; d < 8; d++)
#pragma unroll
            for (int e = 0; e < 4; e++) oacc[d][e] = 0.f;
        float lr = 0.f, lr8 = 0.f;

        for (int kt = 0; kt < nkt; kt++) {
            const int krow = kt * 16 + lrow;
            float sacc[2][4];
#pragma unroll
            for (int nt = 0; nt < 2; nt++)
#pragma unroll
                for (int e = 0; e < 4; e++) sacc[nt][e] = 0.f;
#pragma unroll
            for (int ks = 0; ks < 4; ks++) {
                uint32_t addr = sK + krow * 128 + (((ks * 2 + lseg) ^ (krow & 7)) * 16);
                uint32_t bk[4];
                asm volatile("ldmatrix.sync.aligned.m8n8.x4.shared.b16 {%0,%1,%2,%3}, [%4];"
                             : "=r"(bk[0]), "=r"(bk[1]), "=r"(bk[2]), "=r"(bk[3])
                             : "r"(addr));
#pragma unroll
                for (int nt = 0; nt < 2; nt++) {
                    asm volatile(
                        "mma.sync.aligned.m16n8k16.row.col.f32.f16.f16.f32 "
                        "{%0,%1,%2,%3}, {%4,%5,%6,%7}, {%8,%9}, {%0,%1,%2,%3};"
                        : "+f"(sacc[nt][0]), "+f"(sacc[nt][1]),
                          "+f"(sacc[nt][2]), "+f"(sacc[nt][3])
                        : "r"(aq[ks][0]), "r"(aq[ks][1]), "r"(aq[ks][2]), "r"(aq[ks][3]),
                          "r"(bk[nt]), "r"(bk[nt + 2]));
                }
            }
            float p00 = __expf(fminf(sacc[0][0] * scale, 10.f));
            float p01 = __expf(fminf(sacc[0][1] * scale, 10.f));
            float p02 = __expf(fminf(sacc[0][2] * scale, 10.f));
            float p03 = __expf(fminf(sacc[0][3] * scale, 10.f));
            float p10 = __expf(fminf(sacc[1][0] * scale, 10.f));
            float p11 = __expf(fminf(sacc[1][1] * scale, 10.f));
            float p12 = __expf(fminf(sacc[1][2] * scale, 10.f));
            float p13 = __expf(fminf(sacc[1][3] * scale, 10.f));
            __half2 a0 = __floats2half2_rn(p00, p01);
            __half2 a1 = __floats2half2_rn(p02, p03);
            __half2 a2 = __floats2half2_rn(p10, p11);
            __half2 a3 = __floats2half2_rn(p12, p13);
            float2 f;
            f = __half22float2(a0); lr += f.x + f.y;
            f = __half22float2(a1); lr8 += f.x + f.y;
            f = __half22float2(a2); lr += f.x + f.y;
            f = __half22float2(a3); lr8 += f.x + f.y;
            uint32_t pa0 = *(uint32_t*)&a0, pa1 = *(uint32_t*)&a1;
            uint32_t pa2 = *(uint32_t*)&a2, pa3 = *(uint32_t*)&a3;

#pragma unroll
            for (int v16 = 0; v16 < 4; v16++) {
                uint32_t addr = sV + krow * 128 + (((v16 * 2 + lseg) ^ (krow & 7)) * 16);
                uint32_t bv[4];
                asm volatile("ldmatrix.sync.aligned.m8n8.x4.trans.shared.b16 {%0,%1,%2,%3}, [%4];"
                             : "=r"(bv[0]), "=r"(bv[1]), "=r"(bv[2]), "=r"(bv[3])
                             : "r"(addr));
                asm volatile(
                    "mma.sync.aligned.m16n8k16.row.col.f32.f16.f16.f32 "
                    "{%0,%1,%2,%3}, {%4,%5,%6,%7}, {%8,%9}, {%0,%1,%2,%3};"
                    : "+f"(oacc[v16 * 2][0]), "+f"(oacc[v16 * 2][1]),
                      "+f"(oacc[v16 * 2][2]), "+f"(oacc[v16 * 2][3])
                    : "r"(pa0), "r"(pa1), "r"(pa2), "r"(pa3),
                      "r"(bv[0]), "r"(bv[1]));
                asm volatile(
                    "mma.sync.aligned.m16n8k16.row.col.f32.f16.f16.f32 "
                    "{%0,%1,%2,%3}, {%4,%5,%6,%7}, {%8,%9}, {%0,%1,%2,%3};"
                    : "+f"(oacc[v16 * 2 + 1][0]), "+f"(oacc[v16 * 2 + 1][1]),
                      "+f"(oacc[v16 * 2 + 1][2]), "+f"(oacc[v16 * 2 + 1][3])
                    : "r"(pa0), "r"(pa1), "r"(pa2), "r"(pa3),
                      "r"(bv[2]), "r"(bv[3]));
            }
        }

        lr += __shfl_xor_sync(0xffffffffu, lr, 1);
        lr += __shfl_xor_sync(0xffffffffu, lr, 2);
        lr8 += __shfl_xor_sync(0xffffffffu, lr8, 1);
        lr8 += __shfl_xor_sync(0xffffffffu, lr8, 2);
        float inv = 1.f / (lr - fnpad);
        float inv8 = 1.f / (lr8 - fnpad);

        const int r0 = qt * 16 + (lane >> 2);
#pragma unroll
        for (int dt = 0; dt < 8; dt++) {
            int col = h * HDIM + dt * 8 + (lane & 3) * 2;
            if (r0 < c)
                *(__half2*)(Oh + (size_t)(st + r0) * HID + col) =
                    __floats2half2_rn(oacc[dt][0] * inv, oacc[dt][1] * inv);
            if (r0 + 8 < c)
                *(__half2*)(Oh + (size_t)(st + r0 + 8) * HID + col) =
                    __floats2half2_rn(oacc[dt][2] * inv8, oacc[dt][3] * inv8);
        }
    }
}

// ---------------------------------------------------------------------------
extern "C" void kernel_launch(void* const* d_in, const int* in_sizes, int n_in,
                              void* d_out, int out_size) {
    const float* x  = (const float*)d_in[0];
    const void*  bt = d_in[1];
    const float* wq = (const float*)d_in[2];
    const float* bq = (const float*)d_in[3];
    const float* wk = (const float*)d_in[4];
    const float* bk = (const float*)d_in[5];
    const float* wv = (const float*)d_in[6];
    const float* bv = (const float*)d_in[7];
    const float* wo = (const float*)d_in[8];
    const float* bo = (const float*)d_in[9];
    float* out = (float*)d_out;

    float* bcat;
    __half *QKVh, *Xh, *Wh;
    cudaGetSymbolAddress((void**)&QKVh, g_QKVh);
    cudaGetSymbolAddress((void**)&Xh, g_Xh);
    cudaGetSymbolAddress((void**)&Wh, g_Wh);
    cudaGetSymbolAddress((void**)&bcat, g_bcat);
    __half* Who = Wh + 3 * (size_t)HID * HID;

    const int smem128 = NSTAGE * (16384 + 128 * 128);  // 98304
    const int smem64  = NSTAGE * (16384 + 64 * 128);   // 73728
    cudaFuncSetAttribute(gemm_hmma<128, true>,
                         cudaFuncAttributeMaxDynamicSharedMemorySize, smem128);
    cudaFuncSetAttribute(gemm_hmma<64, false>,
                         cudaFuncAttributeMaxDynamicSharedMemorySize, smem64);
    cudaFuncSetAttribute(attn_tc,
                         cudaFuncAttributeMaxDynamicSharedMemorySize, ATTN_SMEM);

    // fused prep: W/x fp16 convert + segment starts + bias concat
    prep_kernel<<<(PREP_TOT + 255) / 256, 256>>>(
        x, bt, wq, wk, wv, wo, bq, bk, bv, Xh, Wh);

    // fused Q|K|V projection: N = 1536, K = 512, fp16 out
    gemm_hmma<128, true><<<dim3(12, 80), 128, smem128>>>(
        Xh, Wh, bcat, nullptr, QKVh, 1536);

    // tensor-core attention; O -> Xh (fp16)
    attn_tc<<<dim3(NGRAPH, HEADS), 256, ATTN_SMEM>>>(QKVh, Xh);

    // output projection: K = 512, fp32 out
    gemm_hmma<64, false><<<dim3(8, 80), 128, smem64>>>(
        Xh, Who, bo, out, nullptr, 512);
}